// round 6
// baseline (speedup 1.0000x reference)
#include <cuda_runtime.h>
#include <cuda_bf16.h>
#include <math.h>
#include <stdint.h>

#define CDIV(a,b) (((a)+(b)-1)/(b))

typedef unsigned long long ull;

// ---- packed f32x2 helpers (sm_103a FFMA2 path) ------------------------------
__device__ __forceinline__ ull pk2(float x) {
    ull r; asm("mov.b64 %0, {%1, %1};" : "=l"(r) : "f"(x)); return r;
}
__device__ __forceinline__ void ffma2(ull& c, ull a, ull b) {
    asm("fma.rn.f32x2 %0, %1, %2, %0;" : "+l"(c) : "l"(a), "l"(b));
}
__device__ __forceinline__ float2 upk(ull v) {
    float2 f; asm("mov.b64 {%0, %1}, %2;" : "=f"(f.x), "=f"(f.y) : "l"(v)); return f;
}

constexpr int MAXTOK = 130560;     // max(1024*127, 512*255)
constexpr int ELEMS  = 4*64*256*128;

// ---------------------------------------------------------------------------
// Scratch arena (static device memory; no runtime allocation)
// ---------------------------------------------------------------------------
constexpr size_t OF_F    = 0;                               // f    : MAXTOK*128
constexpr size_t OF_QKVR = OF_F    + (size_t)MAXTOK*128;    // qkvr : MAXTOK*1024
constexpr size_t OF_GK   = OF_QKVR + (size_t)MAXTOK*1024;   // gk   : MAXTOK*256
constexpr size_t OF_OG   = OF_GK   + (size_t)MAXTOK*256;    // og   : MAXTOK*256
constexpr size_t OF_T32  = OF_OG   + (size_t)MAXTOK*256;    // t32  : MAXTOK*32
constexpr size_t OF_D01  = OF_T32  + (size_t)MAXTOK*32;     // d01  : MAXTOK*128
constexpr size_t OF_UN   = OF_D01  + (size_t)MAXTOK*128;    // un   : ELEMS
constexpr size_t OF_Y4   = OF_UN   + (size_t)ELEMS;         // y4   : ELEMS
constexpr size_t OF_WF   = OF_Y4   + (size_t)ELEMS;         // wf   : 256*128
constexpr size_t ARENA_TOTAL = OF_WF + (size_t)256*128;

__device__ __align__(128) float g_arena[ARENA_TOTAL];

// bf16 split weights (transposed to [N][K])
__device__ __align__(128) __nv_bfloat16 g_wpT_h[1024*128];
__device__ __align__(128) __nv_bfloat16 g_wpT_l[1024*128];
__device__ __align__(128) __nv_bfloat16 g_wg2T_h[256*32];
__device__ __align__(128) __nv_bfloat16 g_wg2T_l[256*32];
__device__ __align__(128) __nv_bfloat16 g_wfT_h[128*256];
__device__ __align__(128) __nv_bfloat16 g_wfT_l[128*256];

// ---------------------------------------------------------------------------
// bf16 hi/lo split
// ---------------------------------------------------------------------------
__device__ __forceinline__ void bsplit(float x, __nv_bfloat16& h, __nv_bfloat16& l) {
    h = __float2bfloat16_rn(x);
    l = __float2bfloat16_rn(x - __bfloat162float(h));
}

// ---------------------------------------------------------------------------
// Weight prep: transpose + split.
// ---------------------------------------------------------------------------
__global__ void packT_kernel(const float* __restrict__ Wq, const float* __restrict__ Wk,
                             const float* __restrict__ Wv, const float* __restrict__ Wr,
                             __nv_bfloat16* __restrict__ th, __nv_bfloat16* __restrict__ tl)
{
    int idx = blockIdx.x * 256 + threadIdx.x;   // 1024*128
    if (idx >= 1024*128) return;
    int n = idx >> 7, k = idx & 127;
    int grp = n >> 8, nn = n & 255;
    const float* W = (grp == 0) ? Wq : (grp == 1) ? Wk : (grp == 2) ? Wv : Wr;
    float x = W[k*256 + nn] * ((grp == 0) ? 0.125f : 1.f);
    __nv_bfloat16 h, l; bsplit(x, h, l);
    th[idx] = h; tl[idx] = l;
}

__global__ void transT_kernel(const float* __restrict__ W,
                              __nv_bfloat16* __restrict__ th, __nv_bfloat16* __restrict__ tl,
                              int K, int N)
{
    int idx = blockIdx.x * 256 + threadIdx.x;
    if (idx >= N*K) return;
    int n = idx / K, k = idx % K;
    __nv_bfloat16 h, l; bsplit(W[k*N + n], h, l);
    th[idx] = h; tl[idx] = l;
}

// ---------------------------------------------------------------------------
// HMMA plumbing (mma.sync + ldmatrix -- baseline sm_80+ PTX, no arch suffix)
// ---------------------------------------------------------------------------
__device__ __forceinline__ uint32_t s2u(const void* p) {
    uint32_t a;
    asm("{ .reg .u64 t; cvta.to.shared.u64 t, %1; cvt.u32.u64 %0, t; }" : "=r"(a) : "l"(p));
    return a;
}
#define SWZ(x) ((x) ^ (((x) >> 3) & 0x70))

__device__ __forceinline__ void ldm4(uint32_t* r, uint32_t addr) {
    asm volatile("ldmatrix.sync.aligned.m8n8.x4.shared.b16 {%0,%1,%2,%3}, [%4];"
        : "=r"(r[0]), "=r"(r[1]), "=r"(r[2]), "=r"(r[3]) : "r"(addr));
}
__device__ __forceinline__ void mma16816(float* d, const uint32_t* a, uint32_t b0, uint32_t b1) {
    asm volatile("mma.sync.aligned.m16n8k16.row.col.f32.bf16.bf16.f32 "
        "{%0,%1,%2,%3}, {%4,%5,%6,%7}, {%8,%9}, {%0,%1,%2,%3};"
        : "+f"(d[0]), "+f"(d[1]), "+f"(d[2]), "+f"(d[3])
        : "r"(a[0]), "r"(a[1]), "r"(a[2]), "r"(a[3]), "r"(b0), "r"(b1));
}

// ---------------------------------------------------------------------------
// HMMA split-bf16 GEMM: C[M,N] = A[M,K] @ Bt[N,K]^T   (fp32 in/out)
// CTA tile 128x128, 8 warps (4x2), warp tile 32x64, K chunked by 64.
// D = Ah*Bh + Ah*Bl + Al*Bh.  EPI: 0=none, 2=log_sigmoid(z)/32
// Requirements: M%128==0, N%128==0.
// ---------------------------------------------------------------------------
template<int EPI>
__global__ void __launch_bounds__(256, 2)
hmma_gemm(const float* __restrict__ A,
          const __nv_bfloat16* __restrict__ Bh, const __nv_bfloat16* __restrict__ Bl,
          float* __restrict__ C, int M, int N, int K)
{
    extern __shared__ char smem[];
    const uint32_t sb = s2u(smem);
    constexpr int AH = 0;
    constexpr int AL = 16384;
    constexpr int BH = 32768;
    constexpr int BL = 49152;

    const int tid  = threadIdx.x;
    const int m0   = blockIdx.x * 128;
    const int n0   = blockIdx.y * 128;
    const int lane = tid & 31;
    const int w    = tid >> 5;
    const int m0w  = (w & 3) * 32;
    const int n0w  = (w >> 2) * 64;
    const int lrow = lane & 15;
    const int lk8  = (lane >> 4) << 3;

    float d[2][8][4];
    #pragma unroll
    for (int mt = 0; mt < 2; mt++)
        #pragma unroll
        for (int nt = 0; nt < 8; nt++)
            #pragma unroll
            for (int u = 0; u < 4; u++) d[mt][nt][u] = 0.f;

    const int nchunks = (K + 63) >> 6;
    for (int ch = 0; ch < nchunks; ch++) {
        const int kc0 = ch << 6;
        const int Kc  = (K - kc0 < 64) ? (K - kc0) : 64;

        // ---- A tile: 128 x Kc fp32 -> bf16 hi/lo, swizzled 128B rows
        #pragma unroll
        for (int it = 0; it < 8; it++) {
            int i = tid + it*256;
            int r = i >> 4, c4 = (i & 15) * 4;
            ull hp = 0, lp = 0;
            if (c4 < Kc) {
                float4 v = *reinterpret_cast<const float4*>(&A[(size_t)(m0 + r)*K + kc0 + c4]);
                float f[4] = {v.x, v.y, v.z, v.w};
                uint16_t hu[4], lu[4];
                #pragma unroll
                for (int j = 0; j < 4; j++) {
                    __nv_bfloat16 h, l; bsplit(f[j], h, l);
                    hu[j] = __bfloat16_as_ushort(h);
                    lu[j] = __bfloat16_as_ushort(l);
                }
                hp = (ull)hu[0] | ((ull)hu[1] << 16) | ((ull)hu[2] << 32) | ((ull)hu[3] << 48);
                lp = (ull)lu[0] | ((ull)lu[1] << 16) | ((ull)lu[2] << 32) | ((ull)lu[3] << 48);
            }
            int off = SWZ(r*128 + c4*2);
            *reinterpret_cast<ull*>(smem + AH + off) = hp;
            *reinterpret_cast<ull*>(smem + AL + off) = lp;
        }
        // ---- B tile: 128 x Kc bf16 hi/lo (pre-split), swizzled
        #pragma unroll
        for (int it = 0; it < 4; it++) {
            int i = tid + it*256;
            int r = i >> 3, c8 = (i & 7) * 8;
            uint4 hv = make_uint4(0,0,0,0), lv = hv;
            if (c8 < Kc) {
                hv = *reinterpret_cast<const uint4*>(&Bh[(size_t)(n0 + r)*K + kc0 + c8]);
                lv = *reinterpret_cast<const uint4*>(&Bl[(size_t)(n0 + r)*K + kc0 + c8]);
            }
            int off = SWZ(r*128 + c8*2);
            *reinterpret_cast<uint4*>(smem + BH + off) = hv;
            *reinterpret_cast<uint4*>(smem + BL + off) = lv;
        }
        __syncthreads();

        // ---- MMA: ksteps of 16
        const int ksteps = (Kc + 15) >> 4;
        for (int ks = 0; ks < ksteps; ks++) {
            const int kcol = ks*16 + lk8;
            uint32_t ah[2][4], al2[2][4], bb[4][4];
            #pragma unroll
            for (int mt = 0; mt < 2; mt++) {
                uint32_t off = SWZ((m0w + mt*16 + lrow)*128 + kcol*2);
                ldm4(ah[mt],  sb + AH + off);
                ldm4(al2[mt], sb + AL + off);
            }
            #pragma unroll
            for (int nt2 = 0; nt2 < 4; nt2++) {
                uint32_t off = SWZ((n0w + nt2*16 + lrow)*128 + kcol*2);
                ldm4(bb[nt2], sb + BH + off);
            }
            #pragma unroll
            for (int mt = 0; mt < 2; mt++)
                #pragma unroll
                for (int nt = 0; nt < 8; nt++) {
                    uint32_t b0 = (nt & 1) ? bb[nt>>1][1] : bb[nt>>1][0];
                    uint32_t b1 = (nt & 1) ? bb[nt>>1][3] : bb[nt>>1][2];
                    mma16816(d[mt][nt], ah[mt],  b0, b1);   // Ah*Bh
                    mma16816(d[mt][nt], al2[mt], b0, b1);   // Al*Bh
                }
            #pragma unroll
            for (int nt2 = 0; nt2 < 4; nt2++) {
                uint32_t off = SWZ((n0w + nt2*16 + lrow)*128 + kcol*2);
                ldm4(bb[nt2], sb + BL + off);
            }
            #pragma unroll
            for (int mt = 0; mt < 2; mt++)
                #pragma unroll
                for (int nt = 0; nt < 8; nt++) {
                    uint32_t b0 = (nt & 1) ? bb[nt>>1][1] : bb[nt>>1][0];
                    uint32_t b1 = (nt & 1) ? bb[nt>>1][3] : bb[nt>>1][2];
                    mma16816(d[mt][nt], ah[mt], b0, b1);    // Ah*Bl
                }
        }
        __syncthreads();
    }

    // ---- epilogue: fragment (r = lane>>2, c = (lane&3)*2), rows +8 for d2/d3
    const int er = lane >> 2;
    const int ec = (lane & 3) * 2;
    #pragma unroll
    for (int mt = 0; mt < 2; mt++) {
        #pragma unroll
        for (int nt = 0; nt < 8; nt++) {
            float v[4] = {d[mt][nt][0], d[mt][nt][1], d[mt][nt][2], d[mt][nt][3]};
            if (EPI == 2) {
                #pragma unroll
                for (int u = 0; u < 4; u++)
                    v[u] = (fminf(v[u], 0.f) - log1pf(__expf(-fabsf(v[u])))) * (1.f/32.f);
            }
            size_t m = (size_t)(m0 + m0w + mt*16 + er);
            int    n = n0 + n0w + nt*8 + ec;
            *reinterpret_cast<float2*>(&C[m*N + n])        = make_float2(v[0], v[1]);
            *reinterpret_cast<float2*>(&C[(m + 8)*N + n])  = make_float2(v[2], v[3]);
        }
    }
}

// ---------------------------------------------------------------------------
// LayerNorm over channel dim C=64, written in pass layout.
// ---------------------------------------------------------------------------
__global__ void ln_kernel(const float* __restrict__ x,
                          const float* __restrict__ gamma,
                          const float* __restrict__ beta,
                          float* __restrict__ un, int pass)
{
    int idx = blockIdx.x * blockDim.x + threadIdx.x;
    if (idx >= 4*256*128) return;
    int q = idx & 127;
    int t = (idx >> 7) & 255;
    int b = idx >> 15;
    size_t base = ((size_t)b*64*256 + t)*128 + q;
    float sum = 0.f, sq = 0.f;
    #pragma unroll 8
    for (int c = 0; c < 64; c++) {
        float v = x[base + (size_t)c*32768];
        sum += v; sq += v*v;
    }
    float mu  = sum * (1.f/64.f);
    float var = sq  * (1.f/64.f) - mu*mu;
    float inv = rsqrtf(var + 1e-5f);
    #pragma unroll 8
    for (int c = 0; c < 64; c++) {
        float v = (x[base + (size_t)c*32768] - mu) * inv * gamma[c] + beta[c];
        size_t o;
        if (pass == 0) o = (((size_t)(b*256 + t))*64 + c)*128 + q;
        else           o = (((size_t)(b*128 + q))*64 + c)*256 + t;
        un[o] = v;
    }
}

// ---------------------------------------------------------------------------
// Unfold: f[n, l, 2c+k] = un[n, c, l+k]
// ---------------------------------------------------------------------------
__global__ void buildf_kernel(const float* __restrict__ un, float* __restrict__ f,
                              int Nn, int Lf, int L)
{
    size_t idx = (size_t)blockIdx.x * blockDim.x + threadIdx.x;
    size_t total = (size_t)Nn * 64 * L;
    if (idx >= total) return;
    int l = (int)(idx % L);
    int c = (int)((idx / L) % 64);
    int n = (int)(idx / ((size_t)L * 64));
    const float* up = un + ((size_t)n*64 + c)*Lf + l;
    float2 v = make_float2(up[0], up[1]);
    *reinterpret_cast<float2*>(f + ((size_t)n*L + l)*128 + 2*c) = v;
}

// ---------------------------------------------------------------------------
// FFMA2 SGEMM (small shapes): C[M,N] = A[M,K] @ B[K,N]
// ---------------------------------------------------------------------------
template<int EPI, int BN>
__global__ void __launch_bounds__(256, 2)
gemm2_kernel(const float* __restrict__ A, const float* __restrict__ B,
             float* __restrict__ C, int M, int N, int K)
{
    constexpr int TN  = BN / 16;
    constexpr int TN2 = TN / 2;
    __shared__ __align__(16) float As[2][16][132];
    __shared__ __align__(16) float Bs[2][16][BN + 4];

    const int tid = threadIdx.x;
    const int m0  = blockIdx.x * 128;
    const int n0  = blockIdx.y * BN;
    const int rid = tid >> 4;
    const int cid = tid & 15;

    const int ar0 = tid >> 2;
    const int ar1 = ar0 + 64;
    const int ac0 = (tid & 3) * 4;
    const int bkk = tid >> 4;
    const int bnn = (tid & 15) * TN;

    const float* Ap0 = A + (size_t)(m0 + ar0)*K + ac0;
    const float* Ap1 = A + (size_t)(m0 + ar1)*K + ac0;
    const float* Bp  = B + (size_t)bkk*N + n0 + bnn;

    float4 va0, va1, vb0, vb1; float2 vb2;

    va0 = *reinterpret_cast<const float4*>(Ap0);
    va1 = *reinterpret_cast<const float4*>(Ap1);
    if constexpr (TN == 8) {
        vb0 = *reinterpret_cast<const float4*>(Bp);
        vb1 = *reinterpret_cast<const float4*>(Bp + 4);
    } else {
        vb2 = *reinterpret_cast<const float2*>(Bp);
    }
    As[0][ac0+0][ar0] = va0.x; As[0][ac0+1][ar0] = va0.y;
    As[0][ac0+2][ar0] = va0.z; As[0][ac0+3][ar0] = va0.w;
    As[0][ac0+0][ar1] = va1.x; As[0][ac0+1][ar1] = va1.y;
    As[0][ac0+2][ar1] = va1.z; As[0][ac0+3][ar1] = va1.w;
    if constexpr (TN == 8) {
        *reinterpret_cast<float4*>(&Bs[0][bkk][bnn]) = vb0;
        *reinterpret_cast<float4*>(&Bs[0][bkk][bnn + 4]) = vb1;
    } else {
        *reinterpret_cast<float2*>(&Bs[0][bkk][bnn]) = vb2;
    }
    __syncthreads();

    ull acc[8][TN2];
    #pragma unroll
    for (int i = 0; i < 8; i++)
        #pragma unroll
        for (int j = 0; j < TN2; j++) acc[i][j] = 0ull;

    int buf = 0;
    for (int k0 = 0; k0 < K; k0 += 16) {
        const bool nxt = (k0 + 16) < K;
        if (nxt) {
            const int kn = k0 + 16;
            va0 = *reinterpret_cast<const float4*>(Ap0 + kn);
            va1 = *reinterpret_cast<const float4*>(Ap1 + kn);
            if constexpr (TN == 8) {
                vb0 = *reinterpret_cast<const float4*>(Bp + (size_t)kn*N);
                vb1 = *reinterpret_cast<const float4*>(Bp + (size_t)kn*N + 4);
            } else {
                vb2 = *reinterpret_cast<const float2*>(Bp + (size_t)kn*N);
            }
        }
        #pragma unroll
        for (int kk = 0; kk < 16; kk++) {
            float4 a0 = *reinterpret_cast<const float4*>(&As[buf][kk][rid*8]);
            float4 a1 = *reinterpret_cast<const float4*>(&As[buf][kk][rid*8+4]);
            float av[8] = {a0.x,a0.y,a0.z,a0.w,a1.x,a1.y,a1.z,a1.w};
            ull ap[8];
            #pragma unroll
            for (int i = 0; i < 8; i++) ap[i] = pk2(av[i]);
            ull bp[TN2];
            if constexpr (TN == 8) {
                ulonglong2 b01 = *reinterpret_cast<const ulonglong2*>(&Bs[buf][kk][cid*8]);
                ulonglong2 b23 = *reinterpret_cast<const ulonglong2*>(&Bs[buf][kk][cid*8 + 4]);
                bp[0] = b01.x; bp[1] = b01.y; bp[2] = b23.x; bp[3] = b23.y;
            } else {
                bp[0] = *reinterpret_cast<const ull*>(&Bs[buf][kk][cid*2]);
            }
            #pragma unroll
            for (int i = 0; i < 8; i++)
                #pragma unroll
                for (int j = 0; j < TN2; j++)
                    ffma2(acc[i][j], ap[i], bp[j]);
        }
        if (nxt) {
            const int nb = buf ^ 1;
            As[nb][ac0+0][ar0] = va0.x; As[nb][ac0+1][ar0] = va0.y;
            As[nb][ac0+2][ar0] = va0.z; As[nb][ac0+3][ar0] = va0.w;
            As[nb][ac0+0][ar1] = va1.x; As[nb][ac0+1][ar1] = va1.y;
            As[nb][ac0+2][ar1] = va1.z; As[nb][ac0+3][ar1] = va1.w;
            if constexpr (TN == 8) {
                *reinterpret_cast<float4*>(&Bs[nb][bkk][bnn]) = vb0;
                *reinterpret_cast<float4*>(&Bs[nb][bkk][bnn + 4]) = vb1;
            } else {
                *reinterpret_cast<float2*>(&Bs[nb][bkk][bnn]) = vb2;
            }
        }
        __syncthreads();
        buf ^= 1;
    }

    #pragma unroll
    for (int i = 0; i < 8; i++) {
        float out[TN];
        #pragma unroll
        for (int j = 0; j < TN2; j++) {
            float2 f = upk(acc[i][j]);
            out[2*j] = f.x; out[2*j+1] = f.y;
        }
        if (EPI == 2) {
            #pragma unroll
            for (int u = 0; u < TN; u++) {
                float z = out[u];
                out[u] = (fminf(z, 0.f) - log1pf(__expf(-fabsf(z)))) * (1.f/32.f);
            }
        }
        float* crow = C + (size_t)(m0 + rid*8 + i) * N + n0 + cid*TN;
        if constexpr (TN == 8) {
            *reinterpret_cast<float4*>(crow)     = make_float4(out[0],out[1],out[2],out[3]);
            *reinterpret_cast<float4*>(crow + 4) = make_float4(out[4],out[5],out[6],out[7]);
        } else {
            *reinterpret_cast<float2*>(crow) = make_float2(out[0], out[1]);
        }
    }
}

// ---------------------------------------------------------------------------
// Chunked GLA with fused gate (unchanged from round 3)
// ---------------------------------------------------------------------------
__device__ __forceinline__ int swzQ(int t, int d) { return (d + ((t & 3)  << 2)) & 63; }
__device__ __forceinline__ int swzK(int s, int d) { return (d + (s & 28)) & 63; }

__global__ void __launch_bounds__(256)
gla_kernel(const float* __restrict__ qkvr, const float* __restrict__ gkb,
           const float* __restrict__ gnp, float* __restrict__ og,
           int L, int nc)
{
    const int n   = blockIdx.x >> 2;
    const int h   = blockIdx.x & 3;
    const int tid = threadIdx.x;

    __shared__ __align__(16) float S[64][64];
    __shared__ __align__(16) float Qs[32][64];
    __shared__ __align__(16) float Ks[32][64];
    __shared__ __align__(16) float Vs[32][64];
    __shared__ __align__(16) float U[32][64];

    for (int i = tid; i < 64*64; i += 256) (&S[0][0])[i] = 0.f;
    __syncthreads();

    const int glk0 = (tid >> 4) * 4;
    float glr[4];

    for (int c = 0; c < nc; c++) {
        const int lbase = c * 32;

        #pragma unroll
        for (int r = 0; r < 2; r++) {
            int i  = tid + r*256;
            int t  = i >> 4, d4 = (i & 15) * 4;
            int l  = lbase + t;
            float4 gv = make_float4(0.f, 0.f, 0.f, 0.f);
            if (l < L)
                gv = *reinterpret_cast<const float4*>(&gkb[((size_t)(n*L + l))*256 + h*64 + d4]);
            *reinterpret_cast<float4*>(&U[t][d4]) = gv;
        }
        __syncthreads();
        if (tid < 64) {
            float s = 0.f;
            #pragma unroll
            for (int t = 0; t < 32; t++) { s += U[t][tid]; U[t][tid] = s; }
        }
        __syncthreads();
        #pragma unroll
        for (int r = 0; r < 2; r++) {
            int i  = tid + r*256;
            int t  = i >> 4, d4 = (i & 15) * 4;
            int l  = lbase + t;
            float4 qv = make_float4(0,0,0,0), kv = qv, vv = qv;
            if (l < L) {
                size_t base = ((size_t)(n*L + l))*1024 + h*64 + d4;
                qv = *reinterpret_cast<const float4*>(&qkvr[base]);
                kv = *reinterpret_cast<const float4*>(&qkvr[base + 256]);
                vv = *reinterpret_cast<const float4*>(&qkvr[base + 512]);
                float4 g = *reinterpret_cast<const float4*>(&U[t][d4]);
                qv.x *= __expf(g.x);  qv.y *= __expf(g.y);
                qv.z *= __expf(g.z);  qv.w *= __expf(g.w);
                kv.x *= __expf(-g.x); kv.y *= __expf(-g.y);
                kv.z *= __expf(-g.z); kv.w *= __expf(-g.w);
            }
            *reinterpret_cast<float4*>(&Qs[t][swzQ(t, d4)]) = qv;
            *reinterpret_cast<float4*>(&Ks[t][swzK(t, d4)]) = kv;
            *reinterpret_cast<float4*>(&Vs[t][d4]) = vv;
        }
        #pragma unroll
        for (int i = 0; i < 4; i++) glr[i] = U[31][glk0 + i];
        __syncthreads();

        {
            int t  = tid >> 3;
            int s0 = (tid & 7) * 4;
            ull a2[4] = {0ull, 0ull, 0ull, 0ull};
            #pragma unroll
            for (int d = 0; d < 64; d += 4) {
                ulonglong2 qp = *reinterpret_cast<const ulonglong2*>(&Qs[t][swzQ(t, d)]);
                #pragma unroll
                for (int i = 0; i < 4; i++) {
                    ulonglong2 kp = *reinterpret_cast<const ulonglong2*>(&Ks[s0+i][swzK(s0+i, d)]);
                    ffma2(a2[i], qp.x, kp.x);
                    ffma2(a2[i], qp.y, kp.y);
                }
            }
            #pragma unroll
            for (int i = 0; i < 4; i++) {
                float2 f = upk(a2[i]);
                U[t][s0+i] = (s0 + i <= t) ? (f.x + f.y) : 0.f;
            }
        }
        __syncthreads();

        {
            int t   = tid >> 3;
            int dv0 = (tid & 7) * 8;
            ull acc2[4] = {0ull, 0ull, 0ull, 0ull};
            #pragma unroll 8
            for (int s = 0; s < 32; s++) {
                ull ap = pk2(U[t][s]);
                ulonglong2 v0 = *reinterpret_cast<const ulonglong2*>(&Vs[s][dv0]);
                ulonglong2 v1 = *reinterpret_cast<const ulonglong2*>(&Vs[s][dv0+4]);
                ffma2(acc2[0], ap, v0.x); ffma2(acc2[1], ap, v0.y);
                ffma2(acc2[2], ap, v1.x); ffma2(acc2[3], ap, v1.y);
            }
            #pragma unroll 8
            for (int dk = 0; dk < 64; dk++) {
                ull ap = pk2(Qs[t][swzQ(t, dk)]);
                ulonglong2 s0v = *reinterpret_cast<const ulonglong2*>(&S[dk][dv0]);
                ulonglong2 s1v = *reinterpret_cast<const ulonglong2*>(&S[dk][dv0+4]);
                ffma2(acc2[0], ap, s0v.x); ffma2(acc2[1], ap, s0v.y);
                ffma2(acc2[2], ap, s1v.x); ffma2(acc2[3], ap, s1v.y);
            }
            float o8[8];
            #pragma unroll
            for (int j = 0; j < 4; j++) {
                float2 f = upk(acc2[j]);
                o8[2*j] = f.x; o8[2*j+1] = f.y;
            }
            float ss = 0.f;
            #pragma unroll
            for (int j = 0; j < 8; j++) ss += o8[j]*o8[j];
            ss += __shfl_xor_sync(0xFFFFFFFFu, ss, 4, 8);
            ss += __shfl_xor_sync(0xFFFFFFFFu, ss, 2, 8);
            ss += __shfl_xor_sync(0xFFFFFFFFu, ss, 1, 8);
            float inv = rsqrtf(ss * (1.f/64.f) + 1e-5f);
            int l = lbase + t;
            if (l < L) {
                size_t rb = ((size_t)(n*L + l))*1024 + 768 + h*64 + dv0;
                float4 r0 = *reinterpret_cast<const float4*>(&qkvr[rb]);
                float4 r1 = *reinterpret_cast<const float4*>(&qkvr[rb + 4]);
                float4 g0 = *reinterpret_cast<const float4*>(&gnp[h*64 + dv0]);
                float4 g1 = *reinterpret_cast<const float4*>(&gnp[h*64 + dv0 + 4]);
                float rr[8] = {r0.x,r0.y,r0.z,r0.w,r1.x,r1.y,r1.z,r1.w};
                float gg[8] = {g0.x,g0.y,g0.z,g0.w,g1.x,g1.y,g1.z,g1.w};
                float res[8];
                #pragma unroll
                for (int j = 0; j < 8; j++) {
                    float sil = rr[j] / (1.f + __expf(-rr[j]));
                    res[j] = o8[j] * inv * gg[j] * sil;
                }
                float* op = og + ((size_t)(n*L + l))*256 + h*64 + dv0;
                *reinterpret_cast<float4*>(op)     = make_float4(res[0],res[1],res[2],res[3]);
                *reinterpret_cast<float4*>(op + 4) = make_float4(res[4],res[5],res[6],res[7]);
            }
        }
        __syncthreads();

        {
            int dk0 = glk0;
            int dv0 = (tid & 15) * 4;
            ull acc2[4][2] = {{0ull,0ull},{0ull,0ull},{0ull,0ull},{0ull,0ull}};
            #pragma unroll 8
            for (int s = 0; s < 32; s++) {
                float4 k4 = *reinterpret_cast<const float4*>(&Ks[s][swzK(s, dk0)]);
                ulonglong2 vp = *reinterpret_cast<const ulonglong2*>(&Vs[s][dv0]);
                float kk[4] = {k4.x, k4.y, k4.z, k4.w};
                #pragma unroll
                for (int i = 0; i < 4; i++) {
                    ull kp = pk2(kk[i]);
                    ffma2(acc2[i][0], kp, vp.x);
                    ffma2(acc2[i][1], kp, vp.y);
                }
            }
            #pragma unroll
            for (int i = 0; i < 4; i++) {
                float e = __expf(glr[i]);
                float2 f0 = upk(acc2[i][0]);
                float2 f1 = upk(acc2[i][1]);
                float4 sv = *reinterpret_cast<float4*>(&S[dk0+i][dv0]);
                sv.x = e*(sv.x + f0.x);
                sv.y = e*(sv.y + f0.y);
                sv.z = e*(sv.z + f1.x);
                sv.w = e*(sv.w + f1.y);
                *reinterpret_cast<float4*>(&S[dk0+i][dv0]) = sv;
            }
        }
        __syncthreads();
    }
}

// ---------------------------------------------------------------------------
// Deconv combine + residual.
// ---------------------------------------------------------------------------
__global__ void combine_kernel(const float* __restrict__ d01,
                               const float* __restrict__ ctb, const float* __restrict__ resid,
                               float* __restrict__ out, int pass)
{
    int idx = blockIdx.x * blockDim.x + threadIdx.x;
    if (idx >= ELEMS) return;
    int q = idx & 127;
    int t = (idx >> 7) & 255;
    int c = (idx >> 15) & 63;
    int b = idx >> 21;
    float acc = resid[idx] + ctb[c];
    if (pass == 0) {
        int n = b*256 + t;
        if (q < 127) acc += d01[((size_t)n*127 + q    )*128 + 2*c];
        if (q >= 1)  acc += d01[((size_t)n*127 + q - 1)*128 + 2*c + 1];
    } else {
        int n = b*128 + q;
        if (t < 255) acc += d01[((size_t)n*255 + t    )*128 + 2*c];
        if (t >= 1)  acc += d01[((size_t)n*255 + t - 1)*128 + 2*c + 1];
    }
    out[idx] = acc;
}

// ---------------------------------------------------------------------------
// Host side
// ---------------------------------------------------------------------------
struct WPtrs {
    __nv_bfloat16 *wpT_h, *wpT_l, *wg2T_h, *wg2T_l, *wfT_h, *wfT_l;
};

constexpr int HSM = 65536;   // hmma_gemm dynamic smem

static void run_pass(const float* input,
                     const float* gamma, const float* beta,
                     const float* Wq, const float* Wk, const float* Wv,
                     const float* Wg1, const float* Wg2, const float* Wr,
                     const float* gn, const float* Wo,
                     const float* ctw, const float* ctb,
                     const float* resid, float* out,
                     float* A, const WPtrs& W, int pass)
{
    const int N   = pass == 0 ? 1024 : 512;
    const int L   = pass == 0 ? 127  : 255;
    const int Lf  = pass == 0 ? 128  : 256;
    const int nc  = pass == 0 ? 4    : 8;
    const int tok = N * L;
    const int Mt  = tok / 128;

    float* f    = A + OF_F;
    float* qkvr = A + OF_QKVR;
    float* gk   = A + OF_GK;
    float* og   = A + OF_OG;
    float* t32  = A + OF_T32;
    float* d01  = A + OF_D01;
    float* un   = A + OF_UN;
    float* wf   = A + OF_WF;

    // 0. weight prep: transpose + bf16 split
    packT_kernel<<<512, 256>>>(Wq, Wk, Wv, Wr, W.wpT_h, W.wpT_l);
    transT_kernel<<<CDIV(256*32, 256), 256>>>(Wg2, W.wg2T_h, W.wg2T_l, 32, 256);
    gemm2_kernel<0,128><<<dim3(2, 1), 256>>>(Wo, ctw, wf, 256, 128, 128);
    transT_kernel<<<CDIV(128*256, 256), 256>>>(wf, W.wfT_h, W.wfT_l, 256, 128);
    // 1. LayerNorm into pass layout
    ln_kernel<<<CDIV(4*256*128, 256), 256>>>(input, gamma, beta, un, pass);
    // 2. Unfold
    buildf_kernel<<<(unsigned)CDIV((size_t)N*64*L, 256), 256>>>(un, f, N, Lf, L);
    // 3. fused q|k|v|r projection (HMMA split-bf16)
    hmma_gemm<0><<<dim3(Mt, 8), 256, HSM>>>(f, W.wpT_h, W.wpT_l, qkvr, tok, 1024, 128);
    // 4. gk = log_sigmoid(f @ Wg1 @ Wg2) / 32
    gemm2_kernel<0,32><<<dim3(Mt, 1), 256>>>(f, Wg1, t32, tok, 32, 128);
    hmma_gemm<2><<<dim3(Mt, 2), 256, HSM>>>(t32, W.wg2T_h, W.wg2T_l, gk, tok, 256, 32);
    // 5. Chunked GLA with fused RMS-norm + gn + silu(r) gate
    gla_kernel<<<N*4, 256>>>(qkvr, gk, gn, og, L, nc);
    // 6. Output projection + deconv in one GEMM: d01 = og @ Wf
    hmma_gemm<0><<<dim3(Mt, 1), 256, HSM>>>(og, W.wfT_h, W.wfT_l, d01, tok, 128, 256);
    // 7. Shift-combine + bias + residual
    combine_kernel<<<CDIV(ELEMS, 256), 256>>>(d01, ctb, resid, out, pass);
}

extern "C" void kernel_launch(void* const* d_in, const int* in_sizes, int n_in,
                              void* d_out, int out_size)
{
    const float* x = (const float*)d_in[0];
    auto P = [&](int i) { return (const float*)d_in[i]; };

    float* arena = nullptr;
    cudaGetSymbolAddress((void**)&arena, g_arena);
    float* y4 = arena + OF_Y4;

    WPtrs W;
    cudaGetSymbolAddress((void**)&W.wpT_h,  g_wpT_h);
    cudaGetSymbolAddress((void**)&W.wpT_l,  g_wpT_l);
    cudaGetSymbolAddress((void**)&W.wg2T_h, g_wg2T_h);
    cudaGetSymbolAddress((void**)&W.wg2T_l, g_wg2T_l);
    cudaGetSymbolAddress((void**)&W.wfT_h,  g_wfT_h);
    cudaGetSymbolAddress((void**)&W.wfT_l,  g_wfT_l);

    cudaFuncSetAttribute(hmma_gemm<0>, cudaFuncAttributeMaxDynamicSharedMemorySize, HSM);
    cudaFuncSetAttribute(hmma_gemm<2>, cudaFuncAttributeMaxDynamicSharedMemorySize, HSM);

    // Pass 1 (intra): along Q.  params d_in[2..13]
    run_pass(x,
             P(2), P(3), P(4), P(5), P(6), P(7), P(8), P(9), P(10), P(11), P(12), P(13),
             x, y4, arena, W, 0);

    // Pass 2 (inter): along T.  params d_in[14..25]
    run_pass(y4,
             P(14), P(15), P(16), P(17), P(18), P(19), P(20), P(21), P(22), P(23), P(24), P(25),
             y4, (float*)d_out, arena, W, 1);
}

// round 7
// speedup vs baseline: 1.5536x; 1.5536x over previous
#include <cuda_runtime.h>
#include <cuda_bf16.h>
#include <math.h>
#include <stdint.h>

#define CDIV(a,b) (((a)+(b)-1)/(b))
typedef unsigned long long ull;

constexpr int MAXTOK = 130560;
constexpr int ELEMS  = 4*64*256*128;

constexpr size_t OF_F    = 0;
constexpr size_t OF_QKVR = OF_F    + (size_t)MAXTOK*128;
constexpr size_t OF_GK   = OF_QKVR + (size_t)MAXTOK*1024;
constexpr size_t OF_OG   = OF_GK   + (size_t)MAXTOK*256;
constexpr size_t OF_WGG  = OF_OG   + (size_t)MAXTOK*256;    // 128*256
constexpr size_t OF_D01  = OF_WGG  + (size_t)MAXTOK*32;
constexpr size_t OF_UN   = OF_D01  + (size_t)MAXTOK*128;
constexpr size_t OF_Y4   = OF_UN   + (size_t)ELEMS;
constexpr size_t OF_WF   = OF_Y4   + (size_t)ELEMS;
constexpr size_t ARENA_TOTAL = OF_WF + (size_t)256*128;

__device__ __align__(128) float g_arena[ARENA_TOTAL];
__device__ __align__(128) __nv_bfloat16 g_wpT_h[1024*128];
__device__ __align__(128) __nv_bfloat16 g_wpT_l[1024*128];
__device__ __align__(128) __nv_bfloat16 g_wggT_h[256*128];
__device__ __align__(128) __nv_bfloat16 g_wggT_l[256*128];
__device__ __align__(128) __nv_bfloat16 g_wfT_h[128*256];
__device__ __align__(128) __nv_bfloat16 g_wfT_l[128*256];

__device__ __forceinline__ void bsplit(float x, __nv_bfloat16& h, __nv_bfloat16& l) {
    h = __float2bfloat16_rn(x);
    l = __float2bfloat16_rn(x - __bfloat162float(h));
}
__device__ __forceinline__ uint32_t pkbf(float x, float y) {
    uint32_t r; asm("cvt.rn.bf16x2.f32 %0, %1, %2;" : "=r"(r) : "f"(y), "f"(x)); return r;
}
__device__ __forceinline__ void bsplit2(float x0, float x1, uint32_t& hp, uint32_t& lp) {
    hp = pkbf(x0, x1);
    float h0 = __uint_as_float(hp << 16);
    float h1 = __uint_as_float(hp & 0xFFFF0000u);
    lp = pkbf(x0 - h0, x1 - h1);
}

__global__ void packT_kernel(const float* __restrict__ Wq, const float* __restrict__ Wk,
                             const float* __restrict__ Wv, const float* __restrict__ Wr,
                             __nv_bfloat16* __restrict__ th, __nv_bfloat16* __restrict__ tl)
{
    int idx = blockIdx.x * 256 + threadIdx.x;
    if (idx >= 1024*128) return;
    int n = idx >> 7, k = idx & 127;
    int grp = n >> 8, nn = n & 255;
    const float* W = (grp == 0) ? Wq : (grp == 1) ? Wk : (grp == 2) ? Wv : Wr;
    float x = W[k*256 + nn] * ((grp == 0) ? 0.125f : 1.f);
    __nv_bfloat16 h, l; bsplit(x, h, l);
    th[idx] = h; tl[idx] = l;
}
__global__ void transT_kernel(const float* __restrict__ W,
                              __nv_bfloat16* __restrict__ th, __nv_bfloat16* __restrict__ tl,
                              int K, int N)
{
    int idx = blockIdx.x * 256 + threadIdx.x;
    if (idx >= N*K) return;
    int n = idx / K, k = idx % K;
    __nv_bfloat16 h, l; bsplit(W[k*N + n], h, l);
    th[idx] = h; tl[idx] = l;
}
// tiny fp32 GEMM for weight prep: C[M,N] = A[M,K] @ B[K,N]
__global__ void matmul_small(const float* __restrict__ A, const float* __restrict__ B,
                             float* __restrict__ C, int M, int N, int K)
{
    int idx = blockIdx.x * 256 + threadIdx.x;
    if (idx >= M*N) return;
    int m = idx / N, n = idx % N;
    float s = 0.f;
    for (int k = 0; k < K; k++) s += A[m*K + k] * B[k*N + n];
    C[idx] = s;
}

__device__ __forceinline__ uint32_t s2u(const void* p) {
    uint32_t a;
    asm("{ .reg .u64 t; cvta.to.shared.u64 t, %1; cvt.u32.u64 %0, t; }" : "=r"(a) : "l"(p));
    return a;
}
#define SWZ(x) ((x) ^ (((x) >> 3) & 0x70))
__device__ __forceinline__ void ldm4(uint32_t* r, uint32_t addr) {
    asm volatile("ldmatrix.sync.aligned.m8n8.x4.shared.b16 {%0,%1,%2,%3}, [%4];"
        : "=r"(r[0]), "=r"(r[1]), "=r"(r[2]), "=r"(r[3]) : "r"(addr));
}
__device__ __forceinline__ void ldm4t(uint32_t* r, uint32_t addr) {
    asm volatile("ldmatrix.sync.aligned.m8n8.x4.trans.shared.b16 {%0,%1,%2,%3}, [%4];"
        : "=r"(r[0]), "=r"(r[1]), "=r"(r[2]), "=r"(r[3]) : "r"(addr));
}
__device__ __forceinline__ void mma16816(float* d, const uint32_t* a, uint32_t b0, uint32_t b1) {
    asm volatile("mma.sync.aligned.m16n8k16.row.col.f32.bf16.bf16.f32 "
        "{%0,%1,%2,%3}, {%4,%5,%6,%7}, {%8,%9}, {%0,%1,%2,%3};"
        : "+f"(d[0]), "+f"(d[1]), "+f"(d[2]), "+f"(d[3])
        : "r"(a[0]), "r"(a[1]), "r"(a[2]), "r"(a[3]), "r"(b0), "r"(b1));
}

// ---------------------------------------------------------------------------
// HMMA split-bf16 GEMM (validated R5): C[M,N] = A[M,K] @ Bt[N,K]^T
// ---------------------------------------------------------------------------
template<int EPI>
__global__ void __launch_bounds__(256, 2)
hmma_gemm(const float* __restrict__ A,
          const __nv_bfloat16* __restrict__ Bh, const __nv_bfloat16* __restrict__ Bl,
          float* __restrict__ C, int M, int N, int K)
{
    extern __shared__ char smem[];
    const uint32_t sb = s2u(smem);
    constexpr int AH = 0, AL = 16384, BH = 32768, BL = 49152;
    const int tid  = threadIdx.x;
    const int m0   = blockIdx.x * 128;
    const int n0   = blockIdx.y * 128;
    const int lane = tid & 31;
    const int w    = tid >> 5;
    const int m0w  = (w & 3) * 32;
    const int n0w  = (w >> 2) * 64;
    const int lrow = lane & 15;
    const int lk8  = (lane >> 4) << 3;

    float d[2][8][4];
    #pragma unroll
    for (int mt = 0; mt < 2; mt++)
        #pragma unroll
        for (int nt = 0; nt < 8; nt++)
            #pragma unroll
            for (int u = 0; u < 4; u++) d[mt][nt][u] = 0.f;

    const int nchunks = (K + 63) >> 6;
    for (int ch = 0; ch < nchunks; ch++) {
        const int kc0 = ch << 6;
        const int Kc  = (K - kc0 < 64) ? (K - kc0) : 64;
        #pragma unroll
        for (int it = 0; it < 8; it++) {
            int i = tid + it*256;
            int r = i >> 4, c4 = (i & 15) * 4;
            ull hp = 0, lp = 0;
            if (c4 < Kc) {
                float4 v = *reinterpret_cast<const float4*>(&A[(size_t)(m0 + r)*K + kc0 + c4]);
                float f[4] = {v.x, v.y, v.z, v.w};
                uint16_t hu[4], lu[4];
                #pragma unroll
                for (int j = 0; j < 4; j++) {
                    __nv_bfloat16 h, l; bsplit(f[j], h, l);
                    hu[j] = __bfloat16_as_ushort(h);
                    lu[j] = __bfloat16_as_ushort(l);
                }
                hp = (ull)hu[0] | ((ull)hu[1] << 16) | ((ull)hu[2] << 32) | ((ull)hu[3] << 48);
                lp = (ull)lu[0] | ((ull)lu[1] << 16) | ((ull)lu[2] << 32) | ((ull)lu[3] << 48);
            }
            int off = SWZ(r*128 + c4*2);
            *reinterpret_cast<ull*>(smem + AH + off) = hp;
            *reinterpret_cast<ull*>(smem + AL + off) = lp;
        }
        #pragma unroll
        for (int it = 0; it < 4; it++) {
            int i = tid + it*256;
            int r = i >> 3, c8 = (i & 7) * 8;
            uint4 hv = make_uint4(0,0,0,0), lv = hv;
            if (c8 < Kc) {
                hv = *reinterpret_cast<const uint4*>(&Bh[(size_t)(n0 + r)*K + kc0 + c8]);
                lv = *reinterpret_cast<const uint4*>(&Bl[(size_t)(n0 + r)*K + kc0 + c8]);
            }
            int off = SWZ(r*128 + c8*2);
            *reinterpret_cast<uint4*>(smem + BH + off) = hv;
            *reinterpret_cast<uint4*>(smem + BL + off) = lv;
        }
        __syncthreads();
        const int ksteps = (Kc + 15) >> 4;
        for (int ks = 0; ks < ksteps; ks++) {
            const int kcol = ks*16 + lk8;
            uint32_t ah[2][4], al2[2][4], bb[4][4];
            #pragma unroll
            for (int mt = 0; mt < 2; mt++) {
                uint32_t off = SWZ((m0w + mt*16 + lrow)*128 + kcol*2);
                ldm4(ah[mt],  sb + AH + off);
                ldm4(al2[mt], sb + AL + off);
            }
            #pragma unroll
            for (int nt2 = 0; nt2 < 4; nt2++) {
                uint32_t off = SWZ((n0w + nt2*16 + lrow)*128 + kcol*2);
                ldm4(bb[nt2], sb + BH + off);
            }
            #pragma unroll
            for (int mt = 0; mt < 2; mt++)
                #pragma unroll
                for (int nt = 0; nt < 8; nt++) {
                    uint32_t b0 = (nt & 1) ? bb[nt>>1][1] : bb[nt>>1][0];
                    uint32_t b1 = (nt & 1) ? bb[nt>>1][3] : bb[nt>>1][2];
                    mma16816(d[mt][nt], ah[mt],  b0, b1);
                    mma16816(d[mt][nt], al2[mt], b0, b1);
                }
            #pragma unroll
            for (int nt2 = 0; nt2 < 4; nt2++) {
                uint32_t off = SWZ((n0w + nt2*16 + lrow)*128 + kcol*2);
                ldm4(bb[nt2], sb + BL + off);
            }
            #pragma unroll
            for (int mt = 0; mt < 2; mt++)
                #pragma unroll
                for (int nt = 0; nt < 8; nt++) {
                    uint32_t b0 = (nt & 1) ? bb[nt>>1][1] : bb[nt>>1][0];
                    uint32_t b1 = (nt & 1) ? bb[nt>>1][3] : bb[nt>>1][2];
                    mma16816(d[mt][nt], ah[mt], b0, b1);
                }
        }
        __syncthreads();
    }
    const int er = lane >> 2;
    const int ec = (lane & 3) * 2;
    #pragma unroll
    for (int mt = 0; mt < 2; mt++) {
        #pragma unroll
        for (int nt = 0; nt < 8; nt++) {
            float v[4] = {d[mt][nt][0], d[mt][nt][1], d[mt][nt][2], d[mt][nt][3]};
            if (EPI == 2) {
                #pragma unroll
                for (int u = 0; u < 4; u++)
                    v[u] = (fminf(v[u], 0.f) - log1pf(__expf(-fabsf(v[u])))) * (1.f/32.f);
            }
            size_t m = (size_t)(m0 + m0w + mt*16 + er);
            int    n = n0 + n0w + nt*8 + ec;
            *reinterpret_cast<float2*>(&C[m*N + n])        = make_float2(v[0], v[1]);
            *reinterpret_cast<float2*>(&C[(m + 8)*N + n])  = make_float2(v[2], v[3]);
        }
    }
}

__global__ void ln_kernel(const float* __restrict__ x, const float* __restrict__ gamma,
                          const float* __restrict__ beta, float* __restrict__ un, int pass)
{
    int idx = blockIdx.x * blockDim.x + threadIdx.x;
    if (idx >= 4*256*128) return;
    int q = idx & 127, t = (idx >> 7) & 255, b = idx >> 15;
    size_t base = ((size_t)b*64*256 + t)*128 + q;
    float sum = 0.f, sq = 0.f;
    #pragma unroll 8
    for (int c = 0; c < 64; c++) {
        float v = x[base + (size_t)c*32768];
        sum += v; sq += v*v;
    }
    float mu  = sum * (1.f/64.f);
    float inv = rsqrtf(sq * (1.f/64.f) - mu*mu + 1e-5f);
    #pragma unroll 8
    for (int c = 0; c < 64; c++) {
        float v = (x[base + (size_t)c*32768] - mu) * inv * gamma[c] + beta[c];
        size_t o;
        if (pass == 0) o = (((size_t)(b*256 + t))*64 + c)*128 + q;
        else           o = (((size_t)(b*128 + q))*64 + c)*256 + t;
        un[o] = v;
    }
}
__global__ void buildf_kernel(const float* __restrict__ un, float* __restrict__ f,
                              int Nn, int Lf, int L)
{
    size_t idx = (size_t)blockIdx.x * blockDim.x + threadIdx.x;
    if (idx >= (size_t)Nn * 64 * L) return;
    int l = (int)(idx % L);
    int c = (int)((idx / L) % 64);
    int n = (int)(idx / ((size_t)L * 64));
    const float* up = un + ((size_t)n*64 + c)*Lf + l;
    *reinterpret_cast<float2*>(f + ((size_t)n*L + l)*128 + 2*c) = make_float2(up[0], up[1]);
}

// ---------------------------------------------------------------------------
// GLA v4: all matmuls on HMMA split-bf16. One block per (n,h), 8 warps.
// ---------------------------------------------------------------------------
constexpr int G_SH = 0,     G_SL = 8192,  G_S32 = 16384;
constexpr int G_QH = 33792, G_QL = 37888, G_KH = 41984, G_KL = 46080;
constexpr int G_VH = 50176, G_VL = 54272, G_AH = 58368, G_AL = 62464;
constexpr int G_U  = 66560, G_GL = 75264, GSM = 75520;

__global__ void __launch_bounds__(256)
gla_kernel(const float* __restrict__ qkvr, const float* __restrict__ gkb,
           const float* __restrict__ gnp, float* __restrict__ og, int L, int nc)
{
    extern __shared__ char smem[];
    const uint32_t sb = s2u(smem);
    float* Uf  = reinterpret_cast<float*>(smem + G_U);
    float* S32 = reinterpret_cast<float*>(smem + G_S32);
    float* glf = reinterpret_cast<float*>(smem + G_GL);
    const int n = blockIdx.x >> 2, h = blockIdx.x & 3;
    const int tid = threadIdx.x, lane = tid & 31, w = tid >> 5;

    for (int i = tid; i < 33792/4; i += 256) reinterpret_cast<uint32_t*>(smem)[i] = 0u;
    __syncthreads();

    for (int c = 0; c < nc; c++) {
        const int lbase = c * 32;
        // 1. gk chunk -> U
        #pragma unroll
        for (int r = 0; r < 2; r++) {
            int i = tid + r*256, t = i >> 4, d4 = (i & 15) * 4, l = lbase + t;
            float4 gv = make_float4(0,0,0,0);
            if (l < L)
                gv = *reinterpret_cast<const float4*>(&gkb[((size_t)(n*L + l))*256 + h*64 + d4]);
            *reinterpret_cast<float4*>(&Uf[t*68 + d4]) = gv;
        }
        __syncthreads();
        // 2. cumsum + gl
        if (tid < 64) {
            float s = 0.f;
            #pragma unroll
            for (int t = 0; t < 32; t++) { s += Uf[t*68 + tid]; Uf[t*68 + tid] = s; }
            glf[tid] = s;
        }
        __syncthreads();
        // 3. q,k,v -> exp-scaled bf16 hi/lo tiles
        #pragma unroll
        for (int r = 0; r < 2; r++) {
            int i = tid + r*256, t = i >> 4, d4 = (i & 15) * 4, l = lbase + t;
            float4 qv = make_float4(0,0,0,0), kv = qv, vv = qv;
            if (l < L) {
                size_t base = ((size_t)(n*L + l))*1024 + h*64 + d4;
                qv = *reinterpret_cast<const float4*>(&qkvr[base]);
                kv = *reinterpret_cast<const float4*>(&qkvr[base + 256]);
                vv = *reinterpret_cast<const float4*>(&qkvr[base + 512]);
                float4 g = *reinterpret_cast<const float4*>(&Uf[t*68 + d4]);
                qv.x *= __expf(g.x);  qv.y *= __expf(g.y);
                qv.z *= __expf(g.z);  qv.w *= __expf(g.w);
                kv.x *= __expf(-g.x); kv.y *= __expf(-g.y);
                kv.z *= __expf(-g.z); kv.w *= __expf(-g.w);
            }
            uint32_t off = SWZ(t*128 + d4*2);
            uint32_t h0, l0, h1, l1;
            bsplit2(qv.x, qv.y, h0, l0); bsplit2(qv.z, qv.w, h1, l1);
            *reinterpret_cast<uint2*>(smem + G_QH + off) = make_uint2(h0, h1);
            *reinterpret_cast<uint2*>(smem + G_QL + off) = make_uint2(l0, l1);
            bsplit2(kv.x, kv.y, h0, l0); bsplit2(kv.z, kv.w, h1, l1);
            *reinterpret_cast<uint2*>(smem + G_KH + off) = make_uint2(h0, h1);
            *reinterpret_cast<uint2*>(smem + G_KL + off) = make_uint2(l0, l1);
            bsplit2(vv.x, vv.y, h0, l0); bsplit2(vv.z, vv.w, h1, l1);
            *reinterpret_cast<uint2*>(smem + G_VH + off) = make_uint2(h0, h1);
            *reinterpret_cast<uint2*>(smem + G_VL + off) = make_uint2(l0, l1);
        }
        __syncthreads();
        // 4. A = QK^T masked -> Ah/Al. warp: m-tile w&1 (16), n-tile 8*(w>>1)
        {
            const int mrow = 16*(w & 1) + (lane & 15);
            const int s0   = 8*(w >> 1);
            uint32_t kbh[2][4], kbl[2][4];
            #pragma unroll
            for (int g = 0; g < 2; g++) {
                uint32_t off = SWZ((s0 + (lane & 7))*128 + (g*32 + (lane >> 3)*8)*2);
                ldm4(kbh[g], sb + G_KH + off);
                ldm4(kbl[g], sb + G_KL + off);
            }
            float dA[4] = {0,0,0,0};
            #pragma unroll
            for (int ks = 0; ks < 4; ks++) {
                uint32_t ah[4], al[4];
                uint32_t aoff = SWZ(mrow*128 + (ks*16 + (lane >> 4)*8)*2);
                ldm4(ah, sb + G_QH + aoff);
                ldm4(al, sb + G_QL + aoff);
                uint32_t b0h = kbh[ks>>1][(ks&1)*2], b1h = kbh[ks>>1][(ks&1)*2+1];
                uint32_t b0l = kbl[ks>>1][(ks&1)*2], b1l = kbl[ks>>1][(ks&1)*2+1];
                mma16816(dA, ah, b0h, b1h);
                mma16816(dA, ah, b0l, b1l);
                mma16816(dA, al, b0h, b1h);
            }
            int r0 = 16*(w & 1) + (lane >> 2);
            int cc = s0 + 2*(lane & 3);
            float v00 = (cc   <= r0  ) ? dA[0] : 0.f;
            float v01 = (cc+1 <= r0  ) ? dA[1] : 0.f;
            float v10 = (cc   <= r0+8) ? dA[2] : 0.f;
            float v11 = (cc+1 <= r0+8) ? dA[3] : 0.f;
            uint32_t hp, lp;
            bsplit2(v00, v01, hp, lp);
            *reinterpret_cast<uint32_t*>(smem + G_AH + SWZ(r0*128 + cc*2)) = hp;
            *reinterpret_cast<uint32_t*>(smem + G_AL + SWZ(r0*128 + cc*2)) = lp;
            bsplit2(v10, v11, hp, lp);
            *reinterpret_cast<uint32_t*>(smem + G_AH + SWZ((r0+8)*128 + cc*2)) = hp;
            *reinterpret_cast<uint32_t*>(smem + G_AL + SWZ((r0+8)*128 + cc*2)) = lp;
        }
        __syncthreads();
        // 5. o = A@V + Q@S(old) -> U. warp: m-tile w&1, n-base 16*(w>>1)
        {
            const int mrow = 16*(w & 1) + (lane & 15);
            const int nv0  = 16*(w >> 1);
            float d0[4] = {0,0,0,0}, d1[4] = {0,0,0,0};
            #pragma unroll
            for (int ks = 0; ks < 2; ks++) {
                uint32_t ah[4], al[4], vh[4], vl[4];
                uint32_t aoff = SWZ(mrow*128 + (ks*16 + (lane >> 4)*8)*2);
                ldm4(ah, sb + G_AH + aoff);
                ldm4(al, sb + G_AL + aoff);
                uint32_t boff = SWZ((ks*16 + ((lane >> 3) & 1)*8 + (lane & 7))*128
                                    + (nv0 + (lane >> 4)*8)*2);
                ldm4t(vh, sb + G_VH + boff);
                ldm4t(vl, sb + G_VL + boff);
                mma16816(d0, ah, vh[0], vh[1]);
                mma16816(d0, ah, vl[0], vl[1]);
                mma16816(d0, al, vh[0], vh[1]);
                mma16816(d1, ah, vh[2], vh[3]);
                mma16816(d1, ah, vl[2], vl[3]);
                mma16816(d1, al, vh[2], vh[3]);
            }
            #pragma unroll
            for (int ks = 0; ks < 4; ks++) {
                uint32_t qh[4], ql[4], sh[4], sl[4];
                uint32_t aoff = SWZ(mrow*128 + (ks*16 + (lane >> 4)*8)*2);
                ldm4(qh, sb + G_QH + aoff);
                ldm4(ql, sb + G_QL + aoff);
                uint32_t boff = SWZ((ks*16 + ((lane >> 3) & 1)*8 + (lane & 7))*128
                                    + (nv0 + (lane >> 4)*8)*2);
                ldm4t(sh, sb + G_SH + boff);
                ldm4t(sl, sb + G_SL + boff);
                mma16816(d0, qh, sh[0], sh[1]);
                mma16816(d0, qh, sl[0], sl[1]);
                mma16816(d0, ql, sh[0], sh[1]);
                mma16816(d1, qh, sh[2], sh[3]);
                mma16816(d1, qh, sl[2], sl[3]);
                mma16816(d1, ql, sh[2], sh[3]);
            }
            int r0 = 16*(w & 1) + (lane >> 2);
            int c0 = nv0 + 2*(lane & 3);
            *reinterpret_cast<float2*>(&Uf[r0*68 + c0])         = make_float2(d0[0], d0[1]);
            *reinterpret_cast<float2*>(&Uf[(r0+8)*68 + c0])     = make_float2(d0[2], d0[3]);
            *reinterpret_cast<float2*>(&Uf[r0*68 + c0 + 8])     = make_float2(d1[0], d1[1]);
            *reinterpret_cast<float2*>(&Uf[(r0+8)*68 + c0 + 8]) = make_float2(d1[2], d1[3]);
        }
        __syncthreads();
        // 6a. fused gate: RMS-norm * gn * silu(r) -> og
        {
            int t = tid >> 3, dv0 = (tid & 7) * 8;
            float4 oa = *reinterpret_cast<const float4*>(&Uf[t*68 + dv0]);
            float4 obv = *reinterpret_cast<const float4*>(&Uf[t*68 + dv0 + 4]);
            float o8[8] = {oa.x,oa.y,oa.z,oa.w,obv.x,obv.y,obv.z,obv.w};
            float ss = 0.f;
            #pragma unroll
            for (int j = 0; j < 8; j++) ss += o8[j]*o8[j];
            ss += __shfl_xor_sync(0xFFFFFFFFu, ss, 4, 8);
            ss += __shfl_xor_sync(0xFFFFFFFFu, ss, 2, 8);
            ss += __shfl_xor_sync(0xFFFFFFFFu, ss, 1, 8);
            float inv = rsqrtf(ss * (1.f/64.f) + 1e-5f);
            int l = lbase + t;
            if (l < L) {
                size_t rb = ((size_t)(n*L + l))*1024 + 768 + h*64 + dv0;
                float4 r0 = *reinterpret_cast<const float4*>(&qkvr[rb]);
                float4 r1 = *reinterpret_cast<const float4*>(&qkvr[rb + 4]);
                float4 g0 = *reinterpret_cast<const float4*>(&gnp[h*64 + dv0]);
                float4 g1 = *reinterpret_cast<const float4*>(&gnp[h*64 + dv0 + 4]);
                float rr[8] = {r0.x,r0.y,r0.z,r0.w,r1.x,r1.y,r1.z,r1.w};
                float gg[8] = {g0.x,g0.y,g0.z,g0.w,g1.x,g1.y,g1.z,g1.w};
                float res[8];
                #pragma unroll
                for (int j = 0; j < 8; j++)
                    res[j] = o8[j] * inv * gg[j] * (rr[j] / (1.f + __expf(-rr[j])));
                float* op = og + ((size_t)(n*L + l))*256 + h*64 + dv0;
                *reinterpret_cast<float4*>(op)     = make_float4(res[0],res[1],res[2],res[3]);
                *reinterpret_cast<float4*>(op + 4) = make_float4(res[4],res[5],res[6],res[7]);
            }
        }
        // 6b. S = exp(gl)*(S + K^T V); re-split. warp: dk-tile 16*(w&3), dv-base 32*(w>>2)
        {
            const int mk0 = 16*(w & 3);
            const int nb  = 32*(w >> 2);
            float dd[4][4];
            #pragma unroll
            for (int i = 0; i < 4; i++)
                #pragma unroll
                for (int j = 0; j < 4; j++) dd[i][j] = 0.f;
            #pragma unroll
            for (int ks = 0; ks < 2; ks++) {
                uint32_t kh[4], kl[4];
                uint32_t aoff = SWZ((ks*16 + ((lane >> 3) >> 1)*8 + (lane & 7))*128
                                    + (mk0 + ((lane >> 3) & 1)*8)*2);
                ldm4t(kh, sb + G_KH + aoff);
                ldm4t(kl, sb + G_KL + aoff);
                #pragma unroll
                for (int np = 0; np < 2; np++) {
                    uint32_t vh[4], vl[4];
                    uint32_t boff = SWZ((ks*16 + ((lane >> 3) & 1)*8 + (lane & 7))*128
                                        + (nb + 16*np + (lane >> 4)*8)*2);
                    ldm4t(vh, sb + G_VH + boff);
                    ldm4t(vl, sb + G_VL + boff);
                    mma16816(dd[np*2],   kh, vh[0], vh[1]);
                    mma16816(dd[np*2],   kh, vl[0], vl[1]);
                    mma16816(dd[np*2],   kl, vh[0], vh[1]);
                    mma16816(dd[np*2+1], kh, vh[2], vh[3]);
                    mma16816(dd[np*2+1], kh, vl[2], vl[3]);
                    mma16816(dd[np*2+1], kl, vh[2], vh[3]);
                }
            }
            int r0 = mk0 + (lane >> 2);
            float e0 = __expf(glf[r0]);
            float e1 = __expf(glf[r0 + 8]);
            #pragma unroll
            for (int tile = 0; tile < 4; tile++) {
                int cc = nb + ((tile >> 1) * 16) + ((tile & 1) * 8) + 2*(lane & 3);
                float2 s0 = *reinterpret_cast<float2*>(&S32[r0*68 + cc]);
                s0.x = e0*(s0.x + dd[tile][0]);
                s0.y = e0*(s0.y + dd[tile][1]);
                *reinterpret_cast<float2*>(&S32[r0*68 + cc]) = s0;
                float2 s1 = *reinterpret_cast<float2*>(&S32[(r0+8)*68 + cc]);
                s1.x = e1*(s1.x + dd[tile][2]);
                s1.y = e1*(s1.y + dd[tile][3]);
                *reinterpret_cast<float2*>(&S32[(r0+8)*68 + cc]) = s1;
                uint32_t hp, lp;
                bsplit2(s0.x, s0.y, hp, lp);
                *reinterpret_cast<uint32_t*>(smem + G_SH + SWZ(r0*128 + cc*2)) = hp;
                *reinterpret_cast<uint32_t*>(smem + G_SL + SWZ(r0*128 + cc*2)) = lp;
                bsplit2(s1.x, s1.y, hp, lp);
                *reinterpret_cast<uint32_t*>(smem + G_SH + SWZ((r0+8)*128 + cc*2)) = hp;
                *reinterpret_cast<uint32_t*>(smem + G_SL + SWZ((r0+8)*128 + cc*2)) = lp;
            }
        }
        __syncthreads();
    }
}

__global__ void combine_kernel(const float* __restrict__ d01, const float* __restrict__ ctb,
                               const float* __restrict__ resid, float* __restrict__ out, int pass)
{
    int idx = blockIdx.x * blockDim.x + threadIdx.x;
    if (idx >= ELEMS) return;
    int q = idx & 127, t = (idx >> 7) & 255, c = (idx >> 15) & 63, b = idx >> 21;
    float acc = resid[idx] + ctb[c];
    if (pass == 0) {
        int n = b*256 + t;
        if (q < 127) acc += d01[((size_t)n*127 + q    )*128 + 2*c];
        if (q >= 1)  acc += d01[((size_t)n*127 + q - 1)*128 + 2*c + 1];
    } else {
        int n = b*128 + q;
        if (t < 255) acc += d01[((size_t)n*255 + t    )*128 + 2*c];
        if (t >= 1)  acc += d01[((size_t)n*255 + t - 1)*128 + 2*c + 1];
    }
    out[idx] = acc;
}

struct WPtrs {
    __nv_bfloat16 *wpT_h, *wpT_l, *wggT_h, *wggT_l, *wfT_h, *wfT_l;
};
constexpr int HSM = 65536;

static void run_pass(const float* input, const float* gamma, const float* beta,
                     const float* Wq, const float* Wk, const float* Wv,
                     const float* Wg1, const float* Wg2, const float* Wr,
                     const float* gn, const float* Wo,
                     const float* ctw, const float* ctb,
                     const float* resid, float* out,
                     float* A, const WPtrs& W, int pass)
{
    const int N   = pass == 0 ? 1024 : 512;
    const int L   = pass == 0 ? 127  : 255;
    const int Lf  = pass == 0 ? 128  : 256;
    const int nc  = pass == 0 ? 4    : 8;
    const int tok = N * L;
    const int Mt  = tok / 128;

    float* f    = A + OF_F;
    float* qkvr = A + OF_QKVR;
    float* gk   = A + OF_GK;
    float* og   = A + OF_OG;
    float* wgg  = A + OF_WGG;
    float* d01  = A + OF_D01;
    float* un   = A + OF_UN;
    float* wf   = A + OF_WF;

    packT_kernel<<<512, 256>>>(Wq, Wk, Wv, Wr, W.wpT_h, W.wpT_l);
    matmul_small<<<CDIV(128*256, 256), 256>>>(Wg1, Wg2, wgg, 128, 256, 32);
    transT_kernel<<<CDIV(256*128, 256), 256>>>(wgg, W.wggT_h, W.wggT_l, 128, 256);
    matmul_small<<<CDIV(256*128, 256), 256>>>(Wo, ctw, wf, 256, 128, 128);
    transT_kernel<<<CDIV(128*256, 256), 256>>>(wf, W.wfT_h, W.wfT_l, 256, 128);
    ln_kernel<<<CDIV(4*256*128, 256), 256>>>(input, gamma, beta, un, pass);
    buildf_kernel<<<(unsigned)CDIV((size_t)N*64*L, 256), 256>>>(un, f, N, Lf, L);
    hmma_gemm<0><<<dim3(Mt, 8), 256, HSM>>>(f, W.wpT_h, W.wpT_l, qkvr, tok, 1024, 128);
    hmma_gemm<2><<<dim3(Mt, 2), 256, HSM>>>(f, W.wggT_h, W.wggT_l, gk, tok, 256, 128);
    gla_kernel<<<N*4, 256, GSM>>>(qkvr, gk, gn, og, L, nc);
    hmma_gemm<0><<<dim3(Mt, 1), 256, HSM>>>(og, W.wfT_h, W.wfT_l, d01, tok, 128, 256);
    combine_kernel<<<CDIV(ELEMS, 256), 256>>>(d01, ctb, resid, out, pass);
}

extern "C" void kernel_launch(void* const* d_in, const int* in_sizes, int n_in,
                              void* d_out, int out_size)
{
    const float* x = (const float*)d_in[0];
    auto P = [&](int i) { return (const float*)d_in[i]; };

    float* arena = nullptr;
    cudaGetSymbolAddress((void**)&arena, g_arena);
    float* y4 = arena + OF_Y4;

    WPtrs W;
    cudaGetSymbolAddress((void**)&W.wpT_h,  g_wpT_h);
    cudaGetSymbolAddress((void**)&W.wpT_l,  g_wpT_l);
    cudaGetSymbolAddress((void**)&W.wggT_h, g_wggT_h);
    cudaGetSymbolAddress((void**)&W.wggT_l, g_wggT_l);
    cudaGetSymbolAddress((void**)&W.wfT_h,  g_wfT_h);
    cudaGetSymbolAddress((void**)&W.wfT_l,  g_wfT_l);

    cudaFuncSetAttribute(hmma_gemm<0>, cudaFuncAttributeMaxDynamicSharedMemorySize, HSM);
    cudaFuncSetAttribute(hmma_gemm<2>, cudaFuncAttributeMaxDynamicSharedMemorySize, HSM);
    cudaFuncSetAttribute(gla_kernel,   cudaFuncAttributeMaxDynamicSharedMemorySize, GSM);

    run_pass(x, P(2), P(3), P(4), P(5), P(6), P(7), P(8), P(9), P(10), P(11), P(12), P(13),
             x, y4, arena, W, 0);
    run_pass(y4, P(14), P(15), P(16), P(17), P(18), P(19), P(20), P(21), P(22), P(23), P(24), P(25),
             y4, (float*)d_out, arena, W, 1);
}

// round 8
// speedup vs baseline: 1.7855x; 1.1493x over previous
#include <cuda_runtime.h>
#include <cuda_bf16.h>
#include <math.h>
#include <stdint.h>

#define CDIV(a,b) (((a)+(b)-1)/(b))
typedef unsigned long long ull;

constexpr int MAXTOK = 130560;
constexpr int ELEMS  = 4*64*256*128;

constexpr size_t OF_QKVR = 0;
constexpr size_t OF_GK   = OF_QKVR + (size_t)MAXTOK*1024;
constexpr size_t OF_WGG  = OF_GK   + (size_t)MAXTOK*256;
constexpr size_t OF_D01  = OF_WGG  + (size_t)128*256;
constexpr size_t OF_UN   = OF_D01  + (size_t)MAXTOK*128;
constexpr size_t OF_Y4   = OF_UN   + (size_t)ELEMS;
constexpr size_t OF_WF   = OF_Y4   + (size_t)ELEMS;
constexpr size_t ARENA_TOTAL = OF_WF + (size_t)256*128;

__device__ __align__(128) float g_arena[ARENA_TOTAL];
__device__ __align__(128) __nv_bfloat16 g_fh[(size_t)MAXTOK*128];
__device__ __align__(128) __nv_bfloat16 g_fl[(size_t)MAXTOK*128];
__device__ __align__(128) __nv_bfloat16 g_ogh[(size_t)MAXTOK*256];
__device__ __align__(128) __nv_bfloat16 g_ogl[(size_t)MAXTOK*256];
__device__ __align__(128) __nv_bfloat16 g_wpT_h[1024*128];
__device__ __align__(128) __nv_bfloat16 g_wpT_l[1024*128];
__device__ __align__(128) __nv_bfloat16 g_wggT_h[256*128];
__device__ __align__(128) __nv_bfloat16 g_wggT_l[256*128];
__device__ __align__(128) __nv_bfloat16 g_wfT_h[128*256];
__device__ __align__(128) __nv_bfloat16 g_wfT_l[128*256];

__device__ __forceinline__ void bsplit(float x, __nv_bfloat16& h, __nv_bfloat16& l) {
    h = __float2bfloat16_rn(x);
    l = __float2bfloat16_rn(x - __bfloat162float(h));
}
__device__ __forceinline__ uint32_t pkbf(float x, float y) {
    uint32_t r; asm("cvt.rn.bf16x2.f32 %0, %1, %2;" : "=r"(r) : "f"(y), "f"(x)); return r;
}
__device__ __forceinline__ void bsplit2(float x0, float x1, uint32_t& hp, uint32_t& lp) {
    hp = pkbf(x0, x1);
    float h0 = __uint_as_float(hp << 16);
    float h1 = __uint_as_float(hp & 0xFFFF0000u);
    lp = pkbf(x0 - h0, x1 - h1);
}

__global__ void packT_kernel(const float* __restrict__ Wq, const float* __restrict__ Wk,
                             const float* __restrict__ Wv, const float* __restrict__ Wr,
                             __nv_bfloat16* __restrict__ th, __nv_bfloat16* __restrict__ tl)
{
    int idx = blockIdx.x * 256 + threadIdx.x;
    if (idx >= 1024*128) return;
    int n = idx >> 7, k = idx & 127;
    int grp = n >> 8, nn = n & 255;
    const float* W = (grp == 0) ? Wq : (grp == 1) ? Wk : (grp == 2) ? Wv : Wr;
    float x = W[k*256 + nn] * ((grp == 0) ? 0.125f : 1.f);
    __nv_bfloat16 h, l; bsplit(x, h, l);
    th[idx] = h; tl[idx] = l;
}
__global__ void transT_kernel(const float* __restrict__ W,
                              __nv_bfloat16* __restrict__ th, __nv_bfloat16* __restrict__ tl,
                              int K, int N)
{
    int idx = blockIdx.x * 256 + threadIdx.x;
    if (idx >= N*K) return;
    int n = idx / K, k = idx % K;
    __nv_bfloat16 h, l; bsplit(W[k*N + n], h, l);
    th[idx] = h; tl[idx] = l;
}
__global__ void matmul_small(const float* __restrict__ A, const float* __restrict__ B,
                             float* __restrict__ C, int M, int N, int K)
{
    int idx = blockIdx.x * 256 + threadIdx.x;
    if (idx >= M*N) return;
    int m = idx / N, n = idx % N;
    float s = 0.f;
    for (int k = 0; k < K; k++) s += A[m*K + k] * B[k*N + n];
    C[idx] = s;
}

__device__ __forceinline__ uint32_t s2u(const void* p) {
    uint32_t a;
    asm("{ .reg .u64 t; cvta.to.shared.u64 t, %1; cvt.u32.u64 %0, t; }" : "=r"(a) : "l"(p));
    return a;
}
#define SWZ(x) ((x) ^ (((x) >> 3) & 0x70))
__device__ __forceinline__ void ldm4(uint32_t* r, uint32_t addr) {
    asm volatile("ldmatrix.sync.aligned.m8n8.x4.shared.b16 {%0,%1,%2,%3}, [%4];"
        : "=r"(r[0]), "=r"(r[1]), "=r"(r[2]), "=r"(r[3]) : "r"(addr));
}
__device__ __forceinline__ void ldm4t(uint32_t* r, uint32_t addr) {
    asm volatile("ldmatrix.sync.aligned.m8n8.x4.trans.shared.b16 {%0,%1,%2,%3}, [%4];"
        : "=r"(r[0]), "=r"(r[1]), "=r"(r[2]), "=r"(r[3]) : "r"(addr));
}
__device__ __forceinline__ void mma16816(float* d, const uint32_t* a, uint32_t b0, uint32_t b1) {
    asm volatile("mma.sync.aligned.m16n8k16.row.col.f32.bf16.bf16.f32 "
        "{%0,%1,%2,%3}, {%4,%5,%6,%7}, {%8,%9}, {%0,%1,%2,%3};"
        : "+f"(d[0]), "+f"(d[1]), "+f"(d[2]), "+f"(d[3])
        : "r"(a[0]), "r"(a[1]), "r"(a[2]), "r"(a[3]), "r"(b0), "r"(b1));
}
#define CPA16(dst, src) \
    asm volatile("cp.async.cg.shared.global [%0], [%1], 16;" :: "r"(dst), "l"(src))

// ---------------------------------------------------------------------------
// hg2: all-bf16 split GEMM with cp.async double buffering.
// C[M,N] = (Ah+Al)[M,K] @ (Bh+Bl)[N,K]^T (drop Al*Bl). K%64==0, M%128==0, N%128==0.
// Stage = AH|AL|BH|BL 16KB each (128 rows x 128B SW128). 2 stages = 128KB.
// ---------------------------------------------------------------------------
template<int EPI>
__global__ void __launch_bounds__(256, 1)
hg2(const __nv_bfloat16* __restrict__ Ah, const __nv_bfloat16* __restrict__ Al,
    const __nv_bfloat16* __restrict__ Bh, const __nv_bfloat16* __restrict__ Bl,
    float* __restrict__ C, int M, int N, int K)
{
    extern __shared__ char smem[];
    const uint32_t sb = s2u(smem);
    const int tid  = threadIdx.x;
    const int m0   = blockIdx.x * 128;
    const int n0   = blockIdx.y * 128;
    const int lane = tid & 31;
    const int w    = tid >> 5;
    const int m0w  = (w & 3) * 32;
    const int n0w  = (w >> 2) * 64;
    const int lrow = lane & 15;
    const int lk8  = (lane >> 4) << 3;

    auto issue = [&](int ch, int st) {
        const int kc0 = ch << 6;
        const uint32_t sbase = sb + st*65536;
        #pragma unroll
        for (int it = 0; it < 4; it++) {
            int i = tid + it*256;
            int r = i >> 3, g = i & 7;
            uint32_t doff = SWZ(r*128 + g*16);
            size_t aoff = (size_t)(m0 + r)*K + kc0 + g*8;
            size_t boff = (size_t)(n0 + r)*K + kc0 + g*8;
            CPA16(sbase +         doff, Ah + aoff);
            CPA16(sbase + 16384 + doff, Al + aoff);
            CPA16(sbase + 32768 + doff, Bh + boff);
            CPA16(sbase + 49152 + doff, Bl + boff);
        }
        asm volatile("cp.async.commit_group;" ::: "memory");
    };

    float d[2][8][4];
    #pragma unroll
    for (int mt = 0; mt < 2; mt++)
        #pragma unroll
        for (int nt = 0; nt < 8; nt++)
            #pragma unroll
            for (int u = 0; u < 4; u++) d[mt][nt][u] = 0.f;

    const int nch = K >> 6;
    issue(0, 0);
    for (int ch = 0; ch < nch; ch++) {
        const bool nxt = (ch + 1) < nch;
        if (nxt) issue(ch + 1, (ch + 1) & 1);
        if (nxt) asm volatile("cp.async.wait_group 1;" ::: "memory");
        else     asm volatile("cp.async.wait_group 0;" ::: "memory");
        __syncthreads();
        const uint32_t sbase = sb + (ch & 1)*65536;
        #pragma unroll
        for (int ks = 0; ks < 4; ks++) {
            const int kcol = ks*16 + lk8;
            uint32_t ah[2][4], al2[2][4], bb[4][4];
            #pragma unroll
            for (int mt = 0; mt < 2; mt++) {
                uint32_t off = SWZ((m0w + mt*16 + lrow)*128 + kcol*2);
                ldm4(ah[mt],  sbase + off);
                ldm4(al2[mt], sbase + 16384 + off);
            }
            #pragma unroll
            for (int nt2 = 0; nt2 < 4; nt2++) {
                uint32_t off = SWZ((n0w + nt2*16 + lrow)*128 + kcol*2);
                ldm4(bb[nt2], sbase + 32768 + off);
            }
            #pragma unroll
            for (int mt = 0; mt < 2; mt++)
                #pragma unroll
                for (int nt = 0; nt < 8; nt++) {
                    uint32_t b0 = (nt & 1) ? bb[nt>>1][1] : bb[nt>>1][0];
                    uint32_t b1 = (nt & 1) ? bb[nt>>1][3] : bb[nt>>1][2];
                    mma16816(d[mt][nt], ah[mt],  b0, b1);
                    mma16816(d[mt][nt], al2[mt], b0, b1);
                }
            #pragma unroll
            for (int nt2 = 0; nt2 < 4; nt2++) {
                uint32_t off = SWZ((n0w + nt2*16 + lrow)*128 + kcol*2);
                ldm4(bb[nt2], sbase + 49152 + off);
            }
            #pragma unroll
            for (int mt = 0; mt < 2; mt++)
                #pragma unroll
                for (int nt = 0; nt < 8; nt++) {
                    uint32_t b0 = (nt & 1) ? bb[nt>>1][1] : bb[nt>>1][0];
                    uint32_t b1 = (nt & 1) ? bb[nt>>1][3] : bb[nt>>1][2];
                    mma16816(d[mt][nt], ah[mt], b0, b1);
                }
        }
        __syncthreads();
    }

    const int er = lane >> 2;
    const int ec = (lane & 3) * 2;
    #pragma unroll
    for (int mt = 0; mt < 2; mt++) {
        #pragma unroll
        for (int nt = 0; nt < 8; nt++) {
            float v[4] = {d[mt][nt][0], d[mt][nt][1], d[mt][nt][2], d[mt][nt][3]};
            if (EPI == 2) {
                #pragma unroll
                for (int u = 0; u < 4; u++)
                    v[u] = (fminf(v[u], 0.f) - log1pf(__expf(-fabsf(v[u])))) * (1.f/32.f);
            }
            size_t m = (size_t)(m0 + m0w + mt*16 + er);
            int    n = n0 + n0w + nt*8 + ec;
            *reinterpret_cast<float2*>(&C[m*N + n])       = make_float2(v[0], v[1]);
            *reinterpret_cast<float2*>(&C[(m + 8)*N + n]) = make_float2(v[2], v[3]);
        }
    }
}

__global__ void ln_kernel(const float* __restrict__ x, const float* __restrict__ gamma,
                          const float* __restrict__ beta, float* __restrict__ un, int pass)
{
    int idx = blockIdx.x * blockDim.x + threadIdx.x;
    if (idx >= 4*256*128) return;
    int q = idx & 127, t = (idx >> 7) & 255, b = idx >> 15;
    size_t base = ((size_t)b*64*256 + t)*128 + q;
    float sum = 0.f, sq = 0.f;
    #pragma unroll 8
    for (int c = 0; c < 64; c++) {
        float v = x[base + (size_t)c*32768];
        sum += v; sq += v*v;
    }
    float mu  = sum * (1.f/64.f);
    float inv = rsqrtf(sq * (1.f/64.f) - mu*mu + 1e-5f);
    #pragma unroll 8
    for (int c = 0; c < 64; c++) {
        float v = (x[base + (size_t)c*32768] - mu) * inv * gamma[c] + beta[c];
        size_t o;
        if (pass == 0) o = (((size_t)(b*256 + t))*64 + c)*128 + q;
        else           o = (((size_t)(b*128 + q))*64 + c)*256 + t;
        un[o] = v;
    }
}

// f[n][l][2c..2c+1] = (un[n][c][l], un[n][c][l+1]) split to bf16 hi/lo
__global__ void buildf2_kernel(const float* __restrict__ un,
                               __nv_bfloat16* __restrict__ fh, __nv_bfloat16* __restrict__ fl,
                               int Nn, int Lf, int L)
{
    size_t idx = (size_t)blockIdx.x * blockDim.x + threadIdx.x;
    if (idx >= (size_t)Nn * 64 * L) return;
    int l = (int)(idx % L);
    int c = (int)((idx / L) % 64);
    int n = (int)(idx / ((size_t)L * 64));
    const float* up = un + ((size_t)n*64 + c)*Lf + l;
    uint32_t hp, lp;
    bsplit2(up[0], up[1], hp, lp);
    size_t o = (size_t)(n*L + l)*64 + c;
    reinterpret_cast<uint32_t*>(fh)[o] = hp;
    reinterpret_cast<uint32_t*>(fl)[o] = lp;
}

// ---------------------------------------------------------------------------
// GLA v4 (validated R7) — og emitted as bf16 hi/lo
// ---------------------------------------------------------------------------
constexpr int G_SH = 0,     G_SL = 8192,  G_S32 = 16384;
constexpr int G_QH = 33792, G_QL = 37888, G_KH = 41984, G_KL = 46080;
constexpr int G_VH = 50176, G_VL = 54272, G_AH = 58368, G_AL = 62464;
constexpr int G_U  = 66560, G_GL = 75264, GSM = 75520;

__global__ void __launch_bounds__(256)
gla_kernel(const float* __restrict__ qkvr, const float* __restrict__ gkb,
           const float* __restrict__ gnp,
           __nv_bfloat16* __restrict__ ogh, __nv_bfloat16* __restrict__ ogl,
           int L, int nc)
{
    extern __shared__ char smem[];
    const uint32_t sb = s2u(smem);
    float* Uf  = reinterpret_cast<float*>(smem + G_U);
    float* S32 = reinterpret_cast<float*>(smem + G_S32);
    float* glf = reinterpret_cast<float*>(smem + G_GL);
    const int n = blockIdx.x >> 2, h = blockIdx.x & 3;
    const int tid = threadIdx.x, lane = tid & 31, w = tid >> 5;

    for (int i = tid; i < 33792/4; i += 256) reinterpret_cast<uint32_t*>(smem)[i] = 0u;
    __syncthreads();

    for (int c = 0; c < nc; c++) {
        const int lbase = c * 32;
        #pragma unroll
        for (int r = 0; r < 2; r++) {
            int i = tid + r*256, t = i >> 4, d4 = (i & 15) * 4, l = lbase + t;
            float4 gv = make_float4(0,0,0,0);
            if (l < L)
                gv = *reinterpret_cast<const float4*>(&gkb[((size_t)(n*L + l))*256 + h*64 + d4]);
            *reinterpret_cast<float4*>(&Uf[t*68 + d4]) = gv;
        }
        __syncthreads();
        if (tid < 64) {
            float s = 0.f;
            #pragma unroll
            for (int t = 0; t < 32; t++) { s += Uf[t*68 + tid]; Uf[t*68 + tid] = s; }
            glf[tid] = s;
        }
        __syncthreads();
        #pragma unroll
        for (int r = 0; r < 2; r++) {
            int i = tid + r*256, t = i >> 4, d4 = (i & 15) * 4, l = lbase + t;
            float4 qv = make_float4(0,0,0,0), kv = qv, vv = qv;
            if (l < L) {
                size_t base = ((size_t)(n*L + l))*1024 + h*64 + d4;
                qv = *reinterpret_cast<const float4*>(&qkvr[base]);
                kv = *reinterpret_cast<const float4*>(&qkvr[base + 256]);
                vv = *reinterpret_cast<const float4*>(&qkvr[base + 512]);
                float4 g = *reinterpret_cast<const float4*>(&Uf[t*68 + d4]);
                qv.x *= __expf(g.x);  qv.y *= __expf(g.y);
                qv.z *= __expf(g.z);  qv.w *= __expf(g.w);
                kv.x *= __expf(-g.x); kv.y *= __expf(-g.y);
                kv.z *= __expf(-g.z); kv.w *= __expf(-g.w);
            }
            uint32_t off = SWZ(t*128 + d4*2);
            uint32_t h0, l0, h1, l1;
            bsplit2(qv.x, qv.y, h0, l0); bsplit2(qv.z, qv.w, h1, l1);
            *reinterpret_cast<uint2*>(smem + G_QH + off) = make_uint2(h0, h1);
            *reinterpret_cast<uint2*>(smem + G_QL + off) = make_uint2(l0, l1);
            bsplit2(kv.x, kv.y, h0, l0); bsplit2(kv.z, kv.w, h1, l1);
            *reinterpret_cast<uint2*>(smem + G_KH + off) = make_uint2(h0, h1);
            *reinterpret_cast<uint2*>(smem + G_KL + off) = make_uint2(l0, l1);
            bsplit2(vv.x, vv.y, h0, l0); bsplit2(vv.z, vv.w, h1, l1);
            *reinterpret_cast<uint2*>(smem + G_VH + off) = make_uint2(h0, h1);
            *reinterpret_cast<uint2*>(smem + G_VL + off) = make_uint2(l0, l1);
        }
        __syncthreads();
        // A = QK^T masked
        {
            const int mrow = 16*(w & 1) + (lane & 15);
            const int s0   = 8*(w >> 1);
            uint32_t kbh[2][4], kbl[2][4];
            #pragma unroll
            for (int g = 0; g < 2; g++) {
                uint32_t off = SWZ((s0 + (lane & 7))*128 + (g*32 + (lane >> 3)*8)*2);
                ldm4(kbh[g], sb + G_KH + off);
                ldm4(kbl[g], sb + G_KL + off);
            }
            float dA[4] = {0,0,0,0};
            #pragma unroll
            for (int ks = 0; ks < 4; ks++) {
                uint32_t ah[4], al[4];
                uint32_t aoff = SWZ(mrow*128 + (ks*16 + (lane >> 4)*8)*2);
                ldm4(ah, sb + G_QH + aoff);
                ldm4(al, sb + G_QL + aoff);
                uint32_t b0h = kbh[ks>>1][(ks&1)*2], b1h = kbh[ks>>1][(ks&1)*2+1];
                uint32_t b0l = kbl[ks>>1][(ks&1)*2], b1l = kbl[ks>>1][(ks&1)*2+1];
                mma16816(dA, ah, b0h, b1h);
                mma16816(dA, ah, b0l, b1l);
                mma16816(dA, al, b0h, b1h);
            }
            int r0 = 16*(w & 1) + (lane >> 2);
            int cc = s0 + 2*(lane & 3);
            float v00 = (cc   <= r0  ) ? dA[0] : 0.f;
            float v01 = (cc+1 <= r0  ) ? dA[1] : 0.f;
            float v10 = (cc   <= r0+8) ? dA[2] : 0.f;
            float v11 = (cc+1 <= r0+8) ? dA[3] : 0.f;
            uint32_t hp, lp;
            bsplit2(v00, v01, hp, lp);
            *reinterpret_cast<uint32_t*>(smem + G_AH + SWZ(r0*128 + cc*2)) = hp;
            *reinterpret_cast<uint32_t*>(smem + G_AL + SWZ(r0*128 + cc*2)) = lp;
            bsplit2(v10, v11, hp, lp);
            *reinterpret_cast<uint32_t*>(smem + G_AH + SWZ((r0+8)*128 + cc*2)) = hp;
            *reinterpret_cast<uint32_t*>(smem + G_AL + SWZ((r0+8)*128 + cc*2)) = lp;
        }
        __syncthreads();
        // o = A@V + Q@S(old) -> U
        {
            const int mrow = 16*(w & 1) + (lane & 15);
            const int nv0  = 16*(w >> 1);
            float d0[4] = {0,0,0,0}, d1[4] = {0,0,0,0};
            #pragma unroll
            for (int ks = 0; ks < 2; ks++) {
                uint32_t ah[4], al[4], vh[4], vl[4];
                uint32_t aoff = SWZ(mrow*128 + (ks*16 + (lane >> 4)*8)*2);
                ldm4(ah, sb + G_AH + aoff);
                ldm4(al, sb + G_AL + aoff);
                uint32_t boff = SWZ((ks*16 + ((lane >> 3) & 1)*8 + (lane & 7))*128
                                    + (nv0 + (lane >> 4)*8)*2);
                ldm4t(vh, sb + G_VH + boff);
                ldm4t(vl, sb + G_VL + boff);
                mma16816(d0, ah, vh[0], vh[1]);
                mma16816(d0, ah, vl[0], vl[1]);
                mma16816(d0, al, vh[0], vh[1]);
                mma16816(d1, ah, vh[2], vh[3]);
                mma16816(d1, ah, vl[2], vl[3]);
                mma16816(d1, al, vh[2], vh[3]);
            }
            #pragma unroll
            for (int ks = 0; ks < 4; ks++) {
                uint32_t qh[4], ql[4], sh[4], sl[4];
                uint32_t aoff = SWZ(mrow*128 + (ks*16 + (lane >> 4)*8)*2);
                ldm4(qh, sb + G_QH + aoff);
                ldm4(ql, sb + G_QL + aoff);
                uint32_t boff = SWZ((ks*16 + ((lane >> 3) & 1)*8 + (lane & 7))*128
                                    + (nv0 + (lane >> 4)*8)*2);
                ldm4t(sh, sb + G_SH + boff);
                ldm4t(sl, sb + G_SL + boff);
                mma16816(d0, qh, sh[0], sh[1]);
                mma16816(d0, qh, sl[0], sl[1]);
                mma16816(d0, ql, sh[0], sh[1]);
                mma16816(d1, qh, sh[2], sh[3]);
                mma16816(d1, qh, sl[2], sl[3]);
                mma16816(d1, ql, sh[2], sh[3]);
            }
            int r0 = 16*(w & 1) + (lane >> 2);
            int c0 = nv0 + 2*(lane & 3);
            *reinterpret_cast<float2*>(&Uf[r0*68 + c0])         = make_float2(d0[0], d0[1]);
            *reinterpret_cast<float2*>(&Uf[(r0+8)*68 + c0])     = make_float2(d0[2], d0[3]);
            *reinterpret_cast<float2*>(&Uf[r0*68 + c0 + 8])     = make_float2(d1[0], d1[1]);
            *reinterpret_cast<float2*>(&Uf[(r0+8)*68 + c0 + 8]) = make_float2(d1[2], d1[3]);
        }
        __syncthreads();
        // gate epilogue -> og hi/lo
        {
            int t = tid >> 3, dv0 = (tid & 7) * 8;
            float4 oa = *reinterpret_cast<const float4*>(&Uf[t*68 + dv0]);
            float4 obv = *reinterpret_cast<const float4*>(&Uf[t*68 + dv0 + 4]);
            float o8[8] = {oa.x,oa.y,oa.z,oa.w,obv.x,obv.y,obv.z,obv.w};
            float ss = 0.f;
            #pragma unroll
            for (int j = 0; j < 8; j++) ss += o8[j]*o8[j];
            ss += __shfl_xor_sync(0xFFFFFFFFu, ss, 4, 8);
            ss += __shfl_xor_sync(0xFFFFFFFFu, ss, 2, 8);
            ss += __shfl_xor_sync(0xFFFFFFFFu, ss, 1, 8);
            float inv = rsqrtf(ss * (1.f/64.f) + 1e-5f);
            int l = lbase + t;
            if (l < L) {
                size_t rb = ((size_t)(n*L + l))*1024 + 768 + h*64 + dv0;
                float4 r0 = *reinterpret_cast<const float4*>(&qkvr[rb]);
                float4 r1 = *reinterpret_cast<const float4*>(&qkvr[rb + 4]);
                float4 g0 = *reinterpret_cast<const float4*>(&gnp[h*64 + dv0]);
                float4 g1 = *reinterpret_cast<const float4*>(&gnp[h*64 + dv0 + 4]);
                float rr[8] = {r0.x,r0.y,r0.z,r0.w,r1.x,r1.y,r1.z,r1.w};
                float gg[8] = {g0.x,g0.y,g0.z,g0.w,g1.x,g1.y,g1.z,g1.w};
                float res[8];
                #pragma unroll
                for (int j = 0; j < 8; j++)
                    res[j] = o8[j] * inv * gg[j] * (rr[j] / (1.f + __expf(-rr[j])));
                uint32_t hq[4], lq[4];
                #pragma unroll
                for (int j = 0; j < 4; j++) bsplit2(res[2*j], res[2*j+1], hq[j], lq[j]);
                size_t o = ((size_t)(n*L + l)*256 + h*64 + dv0) >> 1;   // u32 index
                *reinterpret_cast<uint4*>(reinterpret_cast<uint32_t*>(ogh) + o)
                    = make_uint4(hq[0], hq[1], hq[2], hq[3]);
                *reinterpret_cast<uint4*>(reinterpret_cast<uint32_t*>(ogl) + o)
                    = make_uint4(lq[0], lq[1], lq[2], lq[3]);
            }
        }
        // S update
        {
            const int mk0 = 16*(w & 3);
            const int nb  = 32*(w >> 2);
            float dd[4][4];
            #pragma unroll
            for (int i = 0; i < 4; i++)
                #pragma unroll
                for (int j = 0; j < 4; j++) dd[i][j] = 0.f;
            #pragma unroll
            for (int ks = 0; ks < 2; ks++) {
                uint32_t kh[4], kl[4];
                uint32_t aoff = SWZ((ks*16 + ((lane >> 3) >> 1)*8 + (lane & 7))*128
                                    + (mk0 + ((lane >> 3) & 1)*8)*2);
                ldm4t(kh, sb + G_KH + aoff);
                ldm4t(kl, sb + G_KL + aoff);
                #pragma unroll
                for (int np = 0; np < 2; np++) {
                    uint32_t vh[4], vl[4];
                    uint32_t boff = SWZ((ks*16 + ((lane >> 3) & 1)*8 + (lane & 7))*128
                                        + (nb + 16*np + (lane >> 4)*8)*2);
                    ldm4t(vh, sb + G_VH + boff);
                    ldm4t(vl, sb + G_VL + boff);
                    mma16816(dd[np*2],   kh, vh[0], vh[1]);
                    mma16816(dd[np*2],   kh, vl[0], vl[1]);
                    mma16816(dd[np*2],   kl, vh[0], vh[1]);
                    mma16816(dd[np*2+1], kh, vh[2], vh[3]);
                    mma16816(dd[np*2+1], kh, vl[2], vl[3]);
                    mma16816(dd[np*2+1], kl, vh[2], vh[3]);
                }
            }
            int r0 = mk0 + (lane >> 2);
            float e0 = __expf(glf[r0]);
            float e1 = __expf(glf[r0 + 8]);
            #pragma unroll
            for (int tile = 0; tile < 4; tile++) {
                int cc = nb + ((tile >> 1) * 16) + ((tile & 1) * 8) + 2*(lane & 3);
                float2 s0 = *reinterpret_cast<float2*>(&S32[r0*68 + cc]);
                s0.x = e0*(s0.x + dd[tile][0]);
                s0.y = e0*(s0.y + dd[tile][1]);
                *reinterpret_cast<float2*>(&S32[r0*68 + cc]) = s0;
                float2 s1 = *reinterpret_cast<float2*>(&S32[(r0+8)*68 + cc]);
                s1.x = e1*(s1.x + dd[tile][2]);
                s1.y = e1*(s1.y + dd[tile][3]);
                *reinterpret_cast<float2*>(&S32[(r0+8)*68 + cc]) = s1;
                uint32_t hp, lp;
                bsplit2(s0.x, s0.y, hp, lp);
                *reinterpret_cast<uint32_t*>(smem + G_SH + SWZ(r0*128 + cc*2)) = hp;
                *reinterpret_cast<uint32_t*>(smem + G_SL + SWZ(r0*128 + cc*2)) = lp;
                bsplit2(s1.x, s1.y, hp, lp);
                *reinterpret_cast<uint32_t*>(smem + G_SH + SWZ((r0+8)*128 + cc*2)) = hp;
                *reinterpret_cast<uint32_t*>(smem + G_SL + SWZ((r0+8)*128 + cc*2)) = lp;
            }
        }
        __syncthreads();
    }
}

__global__ void combine_kernel(const float* __restrict__ d01, const float* __restrict__ ctb,
                               const float* __restrict__ resid, float* __restrict__ out, int pass)
{
    int idx = blockIdx.x * blockDim.x + threadIdx.x;
    if (idx >= ELEMS) return;
    int q = idx & 127, t = (idx >> 7) & 255, c = (idx >> 15) & 63, b = idx >> 21;
    float acc = resid[idx] + ctb[c];
    if (pass == 0) {
        int n = b*256 + t;
        if (q < 127) acc += d01[((size_t)n*127 + q    )*128 + 2*c];
        if (q >= 1)  acc += d01[((size_t)n*127 + q - 1)*128 + 2*c + 1];
    } else {
        int n = b*128 + q;
        if (t < 255) acc += d01[((size_t)n*255 + t    )*128 + 2*c];
        if (t >= 1)  acc += d01[((size_t)n*255 + t - 1)*128 + 2*c + 1];
    }
    out[idx] = acc;
}

struct WPtrs {
    __nv_bfloat16 *wpT_h, *wpT_l, *wggT_h, *wggT_l, *wfT_h, *wfT_l, *fh, *fl, *ogh, *ogl;
};
constexpr int HSM2 = 131072;

static void run_pass(const float* input, const float* gamma, const float* beta,
                     const float* Wq, const float* Wk, const float* Wv,
                     const float* Wg1, const float* Wg2, const float* Wr,
                     const float* gn, const float* Wo,
                     const float* ctw, const float* ctb,
                     const float* resid, float* out,
                     float* A, const WPtrs& W, int pass)
{
    const int N   = pass == 0 ? 1024 : 512;
    const int L   = pass == 0 ? 127  : 255;
    const int Lf  = pass == 0 ? 128  : 256;
    const int nc  = pass == 0 ? 4    : 8;
    const int tok = N * L;
    const int Mt  = tok / 128;

    float* qkvr = A + OF_QKVR;
    float* gk   = A + OF_GK;
    float* wgg  = A + OF_WGG;
    float* d01  = A + OF_D01;
    float* un   = A + OF_UN;
    float* wf   = A + OF_WF;

    packT_kernel<<<512, 256>>>(Wq, Wk, Wv, Wr, W.wpT_h, W.wpT_l);
    matmul_small<<<CDIV(128*256, 256), 256>>>(Wg1, Wg2, wgg, 128, 256, 32);
    transT_kernel<<<CDIV(256*128, 256), 256>>>(wgg, W.wggT_h, W.wggT_l, 128, 256);
    matmul_small<<<CDIV(256*128, 256), 256>>>(Wo, ctw, wf, 256, 128, 128);
    transT_kernel<<<CDIV(128*256, 256), 256>>>(wf, W.wfT_h, W.wfT_l, 256, 128);
    ln_kernel<<<CDIV(4*256*128, 256), 256>>>(input, gamma, beta, un, pass);
    buildf2_kernel<<<(unsigned)CDIV((size_t)N*64*L, 256), 256>>>(un, W.fh, W.fl, N, Lf, L);
    hg2<0><<<dim3(Mt, 8), 256, HSM2>>>(W.fh, W.fl, W.wpT_h, W.wpT_l, qkvr, tok, 1024, 128);
    hg2<2><<<dim3(Mt, 2), 256, HSM2>>>(W.fh, W.fl, W.wggT_h, W.wggT_l, gk, tok, 256, 128);
    gla_kernel<<<N*4, 256, GSM>>>(qkvr, gk, gn, W.ogh, W.ogl, L, nc);
    hg2<0><<<dim3(Mt, 1), 256, HSM2>>>(W.ogh, W.ogl, W.wfT_h, W.wfT_l, d01, tok, 128, 256);
    combine_kernel<<<CDIV(ELEMS, 256), 256>>>(d01, ctb, resid, out, pass);
}

extern "C" void kernel_launch(void* const* d_in, const int* in_sizes, int n_in,
                              void* d_out, int out_size)
{
    const float* x = (const float*)d_in[0];
    auto P = [&](int i) { return (const float*)d_in[i]; };

    float* arena = nullptr;
    cudaGetSymbolAddress((void**)&arena, g_arena);
    float* y4 = arena + OF_Y4;

    WPtrs W;
    cudaGetSymbolAddress((void**)&W.wpT_h,  g_wpT_h);
    cudaGetSymbolAddress((void**)&W.wpT_l,  g_wpT_l);
    cudaGetSymbolAddress((void**)&W.wggT_h, g_wggT_h);
    cudaGetSymbolAddress((void**)&W.wggT_l, g_wggT_l);
    cudaGetSymbolAddress((void**)&W.wfT_h,  g_wfT_h);
    cudaGetSymbolAddress((void**)&W.wfT_l,  g_wfT_l);
    cudaGetSymbolAddress((void**)&W.fh,     g_fh);
    cudaGetSymbolAddress((void**)&W.fl,     g_fl);
    cudaGetSymbolAddress((void**)&W.ogh,    g_ogh);
    cudaGetSymbolAddress((void**)&W.ogl,    g_ogl);

    cudaFuncSetAttribute(hg2<0>, cudaFuncAttributeMaxDynamicSharedMemorySize, HSM2);
    cudaFuncSetAttribute(hg2<2>, cudaFuncAttributeMaxDynamicSharedMemorySize, HSM2);
    cudaFuncSetAttribute(gla_kernel, cudaFuncAttributeMaxDynamicSharedMemorySize, GSM);

    run_pass(x, P(2), P(3), P(4), P(5), P(6), P(7), P(8), P(9), P(10), P(11), P(12), P(13),
             x, y4, arena, W, 0);
    run_pass(y4, P(14), P(15), P(16), P(17), P(18), P(19), P(20), P(21), P(22), P(23), P(24), P(25),
             y4, (float*)d_out, arena, W, 1);
}

// round 9
// speedup vs baseline: 1.9393x; 1.0862x over previous
#include <cuda_runtime.h>
#include <cuda_bf16.h>
#include <math.h>
#include <stdint.h>

#define CDIV(a,b) (((a)+(b)-1)/(b))
typedef unsigned long long ull;

constexpr int MAXTOK = 130560;
constexpr int ELEMS  = 4*64*256*128;

constexpr size_t OF_QKVR = 0;
constexpr size_t OF_GK   = OF_QKVR + (size_t)MAXTOK*1024;
constexpr size_t OF_D01  = OF_GK   + (size_t)MAXTOK*256;
constexpr size_t OF_Y4   = OF_D01  + (size_t)MAXTOK*128;
constexpr size_t ARENA_TOTAL = OF_Y4 + (size_t)ELEMS;

__device__ __align__(128) float g_arena[ARENA_TOTAL];
__device__ __align__(128) __nv_bfloat16 g_fh[(size_t)MAXTOK*128];
__device__ __align__(128) __nv_bfloat16 g_fl[(size_t)MAXTOK*128];
__device__ __align__(128) __nv_bfloat16 g_ogh[(size_t)MAXTOK*256];
__device__ __align__(128) __nv_bfloat16 g_ogl[(size_t)MAXTOK*256];
__device__ __align__(128) __nv_bfloat16 g_wpT_h[1024*128];
__device__ __align__(128) __nv_bfloat16 g_wpT_l[1024*128];
__device__ __align__(128) __nv_bfloat16 g_wggT_h[256*128];
__device__ __align__(128) __nv_bfloat16 g_wggT_l[256*128];
__device__ __align__(128) __nv_bfloat16 g_wfT_h[128*256];
__device__ __align__(128) __nv_bfloat16 g_wfT_l[128*256];

__device__ __forceinline__ void bsplit(float x, __nv_bfloat16& h, __nv_bfloat16& l) {
    h = __float2bfloat16_rn(x);
    l = __float2bfloat16_rn(x - __bfloat162float(h));
}
__device__ __forceinline__ uint32_t pkbf(float x, float y) {
    uint32_t r; asm("cvt.rn.bf16x2.f32 %0, %1, %2;" : "=r"(r) : "f"(y), "f"(x)); return r;
}
__device__ __forceinline__ void bsplit2(float x0, float x1, uint32_t& hp, uint32_t& lp) {
    hp = pkbf(x0, x1);
    float h0 = __uint_as_float(hp << 16);
    float h1 = __uint_as_float(hp & 0xFFFF0000u);
    lp = pkbf(x0 - h0, x1 - h1);
}

__global__ void packT_kernel(const float* __restrict__ Wq, const float* __restrict__ Wk,
                             const float* __restrict__ Wv, const float* __restrict__ Wr,
                             __nv_bfloat16* __restrict__ th, __nv_bfloat16* __restrict__ tl)
{
    int idx = blockIdx.x * 256 + threadIdx.x;
    if (idx >= 1024*128) return;
    int n = idx >> 7, k = idx & 127;
    int grp = n >> 8, nn = n & 255;
    const float* W = (grp == 0) ? Wq : (grp == 1) ? Wk : (grp == 2) ? Wv : Wr;
    float x = W[k*256 + nn] * ((grp == 0) ? 0.125f : 1.f);
    __nv_bfloat16 h, l; bsplit(x, h, l);
    th[idx] = h; tl[idx] = l;
}

// wggT[n*128+k] = sum_j Wg1[k][j] * Wg2[j][n]   (n<256, k<128, j<32)
__global__ void wgg_fused(const float* __restrict__ Wg1, const float* __restrict__ Wg2,
                          __nv_bfloat16* __restrict__ th, __nv_bfloat16* __restrict__ tl)
{
    int idx = blockIdx.x * 256 + threadIdx.x;
    if (idx >= 256*128) return;
    int n = idx >> 7, k = idx & 127;
    float s = 0.f;
    #pragma unroll
    for (int j = 0; j < 32; j++) s += __ldg(&Wg1[k*32 + j]) * __ldg(&Wg2[j*256 + n]);
    __nv_bfloat16 h, l; bsplit(s, h, l);
    th[idx] = h; tl[idx] = l;
}
// wfT[n*256+k] = sum_j Wo[k][j] * ctw[j][n]   (n<128, k<256, j<128; ctw viewed [128][128])
__global__ void wf_fused(const float* __restrict__ Wo, const float* __restrict__ ctw,
                         __nv_bfloat16* __restrict__ th, __nv_bfloat16* __restrict__ tl)
{
    int idx = blockIdx.x * 256 + threadIdx.x;
    if (idx >= 128*256) return;
    int n = idx >> 8, k = idx & 255;
    float s = 0.f;
    #pragma unroll 8
    for (int j = 0; j < 128; j++) s += __ldg(&Wo[k*128 + j]) * __ldg(&ctw[j*128 + n]);
    __nv_bfloat16 h, l; bsplit(s, h, l);
    th[idx] = h; tl[idx] = l;
}

__device__ __forceinline__ uint32_t s2u(const void* p) {
    uint32_t a;
    asm("{ .reg .u64 t; cvta.to.shared.u64 t, %1; cvt.u32.u64 %0, t; }" : "=r"(a) : "l"(p));
    return a;
}
#define SWZ(x) ((x) ^ (((x) >> 3) & 0x70))
__device__ __forceinline__ void ldm4(uint32_t* r, uint32_t addr) {
    asm volatile("ldmatrix.sync.aligned.m8n8.x4.shared.b16 {%0,%1,%2,%3}, [%4];"
        : "=r"(r[0]), "=r"(r[1]), "=r"(r[2]), "=r"(r[3]) : "r"(addr));
}
__device__ __forceinline__ void ldm4t(uint32_t* r, uint32_t addr) {
    asm volatile("ldmatrix.sync.aligned.m8n8.x4.trans.shared.b16 {%0,%1,%2,%3}, [%4];"
        : "=r"(r[0]), "=r"(r[1]), "=r"(r[2]), "=r"(r[3]) : "r"(addr));
}
__device__ __forceinline__ void mma16816(float* d, const uint32_t* a, uint32_t b0, uint32_t b1) {
    asm volatile("mma.sync.aligned.m16n8k16.row.col.f32.bf16.bf16.f32 "
        "{%0,%1,%2,%3}, {%4,%5,%6,%7}, {%8,%9}, {%0,%1,%2,%3};"
        : "+f"(d[0]), "+f"(d[1]), "+f"(d[2]), "+f"(d[3])
        : "r"(a[0]), "r"(a[1]), "r"(a[2]), "r"(a[3]), "r"(b0), "r"(b1));
}
#define CPA16(dst, src) \
    asm volatile("cp.async.cg.shared.global [%0], [%1], 16;" :: "r"(dst), "l"(src))

// ---------------------------------------------------------------------------
// hg2 (validated R8): all-bf16 split GEMM, cp.async double-buffered.
// ---------------------------------------------------------------------------
template<int EPI>
__global__ void __launch_bounds__(256, 1)
hg2(const __nv_bfloat16* __restrict__ Ah, const __nv_bfloat16* __restrict__ Al,
    const __nv_bfloat16* __restrict__ Bh, const __nv_bfloat16* __restrict__ Bl,
    float* __restrict__ C, int M, int N, int K)
{
    extern __shared__ char smem[];
    const uint32_t sb = s2u(smem);
    const int tid  = threadIdx.x;
    const int m0   = blockIdx.x * 128;
    const int n0   = blockIdx.y * 128;
    const int lane = tid & 31;
    const int w    = tid >> 5;
    const int m0w  = (w & 3) * 32;
    const int n0w  = (w >> 2) * 64;
    const int lrow = lane & 15;
    const int lk8  = (lane >> 4) << 3;

    auto issue = [&](int ch, int st) {
        const int kc0 = ch << 6;
        const uint32_t sbase = sb + st*65536;
        #pragma unroll
        for (int it = 0; it < 4; it++) {
            int i = tid + it*256;
            int r = i >> 3, g = i & 7;
            uint32_t doff = SWZ(r*128 + g*16);
            size_t aoff = (size_t)(m0 + r)*K + kc0 + g*8;
            size_t boff = (size_t)(n0 + r)*K + kc0 + g*8;
            CPA16(sbase +         doff, Ah + aoff);
            CPA16(sbase + 16384 + doff, Al + aoff);
            CPA16(sbase + 32768 + doff, Bh + boff);
            CPA16(sbase + 49152 + doff, Bl + boff);
        }
        asm volatile("cp.async.commit_group;" ::: "memory");
    };

    float d[2][8][4];
    #pragma unroll
    for (int mt = 0; mt < 2; mt++)
        #pragma unroll
        for (int nt = 0; nt < 8; nt++)
            #pragma unroll
            for (int u = 0; u < 4; u++) d[mt][nt][u] = 0.f;

    const int nch = K >> 6;
    issue(0, 0);
    for (int ch = 0; ch < nch; ch++) {
        const bool nxt = (ch + 1) < nch;
        if (nxt) issue(ch + 1, (ch + 1) & 1);
        if (nxt) asm volatile("cp.async.wait_group 1;" ::: "memory");
        else     asm volatile("cp.async.wait_group 0;" ::: "memory");
        __syncthreads();
        const uint32_t sbase = sb + (ch & 1)*65536;
        #pragma unroll
        for (int ks = 0; ks < 4; ks++) {
            const int kcol = ks*16 + lk8;
            uint32_t ah[2][4], al2[2][4], bb[4][4];
            #pragma unroll
            for (int mt = 0; mt < 2; mt++) {
                uint32_t off = SWZ((m0w + mt*16 + lrow)*128 + kcol*2);
                ldm4(ah[mt],  sbase + off);
                ldm4(al2[mt], sbase + 16384 + off);
            }
            #pragma unroll
            for (int nt2 = 0; nt2 < 4; nt2++) {
                uint32_t off = SWZ((n0w + nt2*16 + lrow)*128 + kcol*2);
                ldm4(bb[nt2], sbase + 32768 + off);
            }
            #pragma unroll
            for (int mt = 0; mt < 2; mt++)
                #pragma unroll
                for (int nt = 0; nt < 8; nt++) {
                    uint32_t b0 = (nt & 1) ? bb[nt>>1][1] : bb[nt>>1][0];
                    uint32_t b1 = (nt & 1) ? bb[nt>>1][3] : bb[nt>>1][2];
                    mma16816(d[mt][nt], ah[mt],  b0, b1);
                    mma16816(d[mt][nt], al2[mt], b0, b1);
                }
            #pragma unroll
            for (int nt2 = 0; nt2 < 4; nt2++) {
                uint32_t off = SWZ((n0w + nt2*16 + lrow)*128 + kcol*2);
                ldm4(bb[nt2], sbase + 49152 + off);
            }
            #pragma unroll
            for (int mt = 0; mt < 2; mt++)
                #pragma unroll
                for (int nt = 0; nt < 8; nt++) {
                    uint32_t b0 = (nt & 1) ? bb[nt>>1][1] : bb[nt>>1][0];
                    uint32_t b1 = (nt & 1) ? bb[nt>>1][3] : bb[nt>>1][2];
                    mma16816(d[mt][nt], ah[mt], b0, b1);
                }
        }
        __syncthreads();
    }

    const int er = lane >> 2;
    const int ec = (lane & 3) * 2;
    #pragma unroll
    for (int mt = 0; mt < 2; mt++) {
        #pragma unroll
        for (int nt = 0; nt < 8; nt++) {
            float v[4] = {d[mt][nt][0], d[mt][nt][1], d[mt][nt][2], d[mt][nt][3]};
            if (EPI == 2) {
                #pragma unroll
                for (int u = 0; u < 4; u++)
                    v[u] = (fminf(v[u], 0.f) - log1pf(__expf(-fabsf(v[u])))) * (1.f/32.f);
            }
            size_t m = (size_t)(m0 + m0w + mt*16 + er);
            int    n = n0 + n0w + nt*8 + ec;
            *reinterpret_cast<float2*>(&C[m*N + n])       = make_float2(v[0], v[1]);
            *reinterpret_cast<float2*>(&C[(m + 8)*N + n]) = make_float2(v[2], v[3]);
        }
    }
}

// ---------------------------------------------------------------------------
// Fused LN + unfold, pass 0 (unfold along q). One block per (b,t), 128 thr.
// ---------------------------------------------------------------------------
__global__ void __launch_bounds__(128)
lnf0_kernel(const float* __restrict__ x, const float* __restrict__ gamma,
            const float* __restrict__ beta,
            __nv_bfloat16* __restrict__ fh, __nv_bfloat16* __restrict__ fl)
{
    __shared__ float U[64][129];
    const int tid = threadIdx.x;               // q
    const int b = blockIdx.x >> 8, t = blockIdx.x & 255;
    const int n = blockIdx.x;                  // b*256 + t
    #pragma unroll 8
    for (int c = 0; c < 64; c++)
        U[c][tid] = x[(((size_t)b*64 + c)*256 + t)*128 + tid];
    __syncthreads();
    float sum = 0.f, sq = 0.f;
    #pragma unroll 8
    for (int c = 0; c < 64; c++) { float v = U[c][tid]; sum += v; sq += v*v; }
    float mu  = sum * (1.f/64.f);
    float inv = rsqrtf(sq * (1.f/64.f) - mu*mu + 1e-5f);
    #pragma unroll 8
    for (int c = 0; c < 64; c++)
        U[c][tid] = (U[c][tid] - mu) * inv * gamma[c] + beta[c];
    __syncthreads();
    uint32_t* fhp = reinterpret_cast<uint32_t*>(fh);
    uint32_t* flp = reinterpret_cast<uint32_t*>(fl);
    #pragma unroll 4
    for (int it = 0; it < 64; it++) {
        int idx = it*128 + tid;
        int l = idx >> 6, c = idx & 63;
        if (l >= 127) continue;                // L = 127
        uint32_t hp, lp;
        bsplit2(U[c][l], U[c][l+1], hp, lp);
        size_t o = (size_t)(n*127 + l)*64 + c;
        fhp[o] = hp; flp[o] = lp;
    }
}

// ---------------------------------------------------------------------------
// Fused LN + unfold, pass 1 (unfold along t). Block = (b, q-tile 32, t-tile 8).
// Loads 9 t-slabs (halo). 256 threads, dynamic smem 9*64*33*4 = 76032 B.
// ---------------------------------------------------------------------------
__global__ void __launch_bounds__(256)
lnf1_kernel(const float* __restrict__ x, const float* __restrict__ gamma,
            const float* __restrict__ beta,
            __nv_bfloat16* __restrict__ fh, __nv_bfloat16* __restrict__ fl)
{
    extern __shared__ float Us[];              // [tl][c][q] : [9][64][33]
    const int tid = threadIdx.x;
    const int tt = blockIdx.x & 31;            // t-tile (32)
    const int qt = (blockIdx.x >> 5) & 3;      // q-tile (4)
    const int b  = blockIdx.x >> 7;
    const int t0 = tt*8, q0 = qt*32;
    auto UI = [&](int tl, int c, int q) -> float& { return Us[(tl*64 + c)*33 + q]; };

    #pragma unroll
    for (int it = 0; it < 72; it++) {          // 9*64*32 / 256
        int idx = it*256 + tid;
        int q = idx & 31, c = (idx >> 5) & 63, tl = idx >> 11;
        int t = t0 + tl;
        UI(tl, c, q) = (t < 256) ? x[(((size_t)b*64 + c)*256 + t)*128 + q0 + q] : 0.f;
    }
    __syncthreads();
    // stats + normalize per (tl 0..8, q 0..31)
    for (int pair = tid; pair < 288; pair += 256) {
        int tl = pair >> 5, q = pair & 31;
        float sum = 0.f, sq = 0.f;
        #pragma unroll 8
        for (int c = 0; c < 64; c++) { float v = UI(tl, c, q); sum += v; sq += v*v; }
        float mu  = sum * (1.f/64.f);
        float inv = rsqrtf(sq * (1.f/64.f) - mu*mu + 1e-5f);
        #pragma unroll 8
        for (int c = 0; c < 64; c++)
            UI(tl, c, q) = (UI(tl, c, q) - mu) * inv * gamma[c] + beta[c];
    }
    __syncthreads();
    uint32_t* fhp = reinterpret_cast<uint32_t*>(fh);
    uint32_t* flp = reinterpret_cast<uint32_t*>(fl);
    #pragma unroll 4
    for (int it = 0; it < 64; it++) {          // 8*64*32 / 256
        int idx = it*256 + tid;
        int c = idx & 63, tl = (idx >> 6) & 7, q = idx >> 9;
        int l = t0 + tl;
        if (l >= 255) continue;                // L = 255
        uint32_t hp, lp;
        bsplit2(UI(tl, c, q), UI(tl+1, c, q), hp, lp);
        size_t o = ((size_t)(b*128 + q0 + q)*255 + l)*64 + c;
        fhp[o] = hp; flp[o] = lp;
    }
}

// ---------------------------------------------------------------------------
// GLA v4 (validated) — og emitted as bf16 hi/lo
// ---------------------------------------------------------------------------
constexpr int G_SH = 0,     G_SL = 8192,  G_S32 = 16384;
constexpr int G_QH = 33792, G_QL = 37888, G_KH = 41984, G_KL = 46080;
constexpr int G_VH = 50176, G_VL = 54272, G_AH = 58368, G_AL = 62464;
constexpr int G_U  = 66560, G_GL = 75264, GSM = 75520;

__global__ void __launch_bounds__(256)
gla_kernel(const float* __restrict__ qkvr, const float* __restrict__ gkb,
           const float* __restrict__ gnp,
           __nv_bfloat16* __restrict__ ogh, __nv_bfloat16* __restrict__ ogl,
           int L, int nc)
{
    extern __shared__ char smem[];
    const uint32_t sb = s2u(smem);
    float* Uf  = reinterpret_cast<float*>(smem + G_U);
    float* S32 = reinterpret_cast<float*>(smem + G_S32);
    float* glf = reinterpret_cast<float*>(smem + G_GL);
    const int n = blockIdx.x >> 2, h = blockIdx.x & 3;
    const int tid = threadIdx.x, lane = tid & 31, w = tid >> 5;

    for (int i = tid; i < 33792/4; i += 256) reinterpret_cast<uint32_t*>(smem)[i] = 0u;
    __syncthreads();

    for (int c = 0; c < nc; c++) {
        const int lbase = c * 32;
        #pragma unroll
        for (int r = 0; r < 2; r++) {
            int i = tid + r*256, t = i >> 4, d4 = (i & 15) * 4, l = lbase + t;
            float4 gv = make_float4(0,0,0,0);
            if (l < L)
                gv = *reinterpret_cast<const float4*>(&gkb[((size_t)(n*L + l))*256 + h*64 + d4]);
            *reinterpret_cast<float4*>(&Uf[t*68 + d4]) = gv;
        }
        __syncthreads();
        if (tid < 64) {
            float s = 0.f;
            #pragma unroll
            for (int t = 0; t < 32; t++) { s += Uf[t*68 + tid]; Uf[t*68 + tid] = s; }
            glf[tid] = s;
        }
        __syncthreads();
        #pragma unroll
        for (int r = 0; r < 2; r++) {
            int i = tid + r*256, t = i >> 4, d4 = (i & 15) * 4, l = lbase + t;
            float4 qv = make_float4(0,0,0,0), kv = qv, vv = qv;
            if (l < L) {
                size_t base = ((size_t)(n*L + l))*1024 + h*64 + d4;
                qv = *reinterpret_cast<const float4*>(&qkvr[base]);
                kv = *reinterpret_cast<const float4*>(&qkvr[base + 256]);
                vv = *reinterpret_cast<const float4*>(&qkvr[base + 512]);
                float4 g = *reinterpret_cast<const float4*>(&Uf[t*68 + d4]);
                qv.x *= __expf(g.x);  qv.y *= __expf(g.y);
                qv.z *= __expf(g.z);  qv.w *= __expf(g.w);
                kv.x *= __expf(-g.x); kv.y *= __expf(-g.y);
                kv.z *= __expf(-g.z); kv.w *= __expf(-g.w);
            }
            uint32_t off = SWZ(t*128 + d4*2);
            uint32_t h0, l0, h1, l1;
            bsplit2(qv.x, qv.y, h0, l0); bsplit2(qv.z, qv.w, h1, l1);
            *reinterpret_cast<uint2*>(smem + G_QH + off) = make_uint2(h0, h1);
            *reinterpret_cast<uint2*>(smem + G_QL + off) = make_uint2(l0, l1);
            bsplit2(kv.x, kv.y, h0, l0); bsplit2(kv.z, kv.w, h1, l1);
            *reinterpret_cast<uint2*>(smem + G_KH + off) = make_uint2(h0, h1);
            *reinterpret_cast<uint2*>(smem + G_KL + off) = make_uint2(l0, l1);
            bsplit2(vv.x, vv.y, h0, l0); bsplit2(vv.z, vv.w, h1, l1);
            *reinterpret_cast<uint2*>(smem + G_VH + off) = make_uint2(h0, h1);
            *reinterpret_cast<uint2*>(smem + G_VL + off) = make_uint2(l0, l1);
        }
        __syncthreads();
        // A = QK^T masked
        {
            const int mrow = 16*(w & 1) + (lane & 15);
            const int s0   = 8*(w >> 1);
            uint32_t kbh[2][4], kbl[2][4];
            #pragma unroll
            for (int g = 0; g < 2; g++) {
                uint32_t off = SWZ((s0 + (lane & 7))*128 + (g*32 + (lane >> 3)*8)*2);
                ldm4(kbh[g], sb + G_KH + off);
                ldm4(kbl[g], sb + G_KL + off);
            }
            float dA[4] = {0,0,0,0};
            #pragma unroll
            for (int ks = 0; ks < 4; ks++) {
                uint32_t ah[4], al[4];
                uint32_t aoff = SWZ(mrow*128 + (ks*16 + (lane >> 4)*8)*2);
                ldm4(ah, sb + G_QH + aoff);
                ldm4(al, sb + G_QL + aoff);
                uint32_t b0h = kbh[ks>>1][(ks&1)*2], b1h = kbh[ks>>1][(ks&1)*2+1];
                uint32_t b0l = kbl[ks>>1][(ks&1)*2], b1l = kbl[ks>>1][(ks&1)*2+1];
                mma16816(dA, ah, b0h, b1h);
                mma16816(dA, ah, b0l, b1l);
                mma16816(dA, al, b0h, b1h);
            }
            int r0 = 16*(w & 1) + (lane >> 2);
            int cc = s0 + 2*(lane & 3);
            float v00 = (cc   <= r0  ) ? dA[0] : 0.f;
            float v01 = (cc+1 <= r0  ) ? dA[1] : 0.f;
            float v10 = (cc   <= r0+8) ? dA[2] : 0.f;
            float v11 = (cc+1 <= r0+8) ? dA[3] : 0.f;
            uint32_t hp, lp;
            bsplit2(v00, v01, hp, lp);
            *reinterpret_cast<uint32_t*>(smem + G_AH + SWZ(r0*128 + cc*2)) = hp;
            *reinterpret_cast<uint32_t*>(smem + G_AL + SWZ(r0*128 + cc*2)) = lp;
            bsplit2(v10, v11, hp, lp);
            *reinterpret_cast<uint32_t*>(smem + G_AH + SWZ((r0+8)*128 + cc*2)) = hp;
            *reinterpret_cast<uint32_t*>(smem + G_AL + SWZ((r0+8)*128 + cc*2)) = lp;
        }
        __syncthreads();
        // o = A@V + Q@S(old) -> U
        {
            const int mrow = 16*(w & 1) + (lane & 15);
            const int nv0  = 16*(w >> 1);
            float d0[4] = {0,0,0,0}, d1[4] = {0,0,0,0};
            #pragma unroll
            for (int ks = 0; ks < 2; ks++) {
                uint32_t ah[4], al[4], vh[4], vl[4];
                uint32_t aoff = SWZ(mrow*128 + (ks*16 + (lane >> 4)*8)*2);
                ldm4(ah, sb + G_AH + aoff);
                ldm4(al, sb + G_AL + aoff);
                uint32_t boff = SWZ((ks*16 + ((lane >> 3) & 1)*8 + (lane & 7))*128
                                    + (nv0 + (lane >> 4)*8)*2);
                ldm4t(vh, sb + G_VH + boff);
                ldm4t(vl, sb + G_VL + boff);
                mma16816(d0, ah, vh[0], vh[1]);
                mma16816(d0, ah, vl[0], vl[1]);
                mma16816(d0, al, vh[0], vh[1]);
                mma16816(d1, ah, vh[2], vh[3]);
                mma16816(d1, ah, vl[2], vl[3]);
                mma16816(d1, al, vh[2], vh[3]);
            }
            #pragma unroll
            for (int ks = 0; ks < 4; ks++) {
                uint32_t qh[4], ql[4], sh[4], sl[4];
                uint32_t aoff = SWZ(mrow*128 + (ks*16 + (lane >> 4)*8)*2);
                ldm4(qh, sb + G_QH + aoff);
                ldm4(ql, sb + G_QL + aoff);
                uint32_t boff = SWZ((ks*16 + ((lane >> 3) & 1)*8 + (lane & 7))*128
                                    + (nv0 + (lane >> 4)*8)*2);
                ldm4t(sh, sb + G_SH + boff);
                ldm4t(sl, sb + G_SL + boff);
                mma16816(d0, qh, sh[0], sh[1]);
                mma16816(d0, qh, sl[0], sl[1]);
                mma16816(d0, ql, sh[0], sh[1]);
                mma16816(d1, qh, sh[2], sh[3]);
                mma16816(d1, qh, sl[2], sl[3]);
                mma16816(d1, ql, sh[2], sh[3]);
            }
            int r0 = 16*(w & 1) + (lane >> 2);
            int c0 = nv0 + 2*(lane & 3);
            *reinterpret_cast<float2*>(&Uf[r0*68 + c0])         = make_float2(d0[0], d0[1]);
            *reinterpret_cast<float2*>(&Uf[(r0+8)*68 + c0])     = make_float2(d0[2], d0[3]);
            *reinterpret_cast<float2*>(&Uf[r0*68 + c0 + 8])     = make_float2(d1[0], d1[1]);
            *reinterpret_cast<float2*>(&Uf[(r0+8)*68 + c0 + 8]) = make_float2(d1[2], d1[3]);
        }
        __syncthreads();
        // gate epilogue -> og hi/lo
        {
            int t = tid >> 3, dv0 = (tid & 7) * 8;
            float4 oa = *reinterpret_cast<const float4*>(&Uf[t*68 + dv0]);
            float4 obv = *reinterpret_cast<const float4*>(&Uf[t*68 + dv0 + 4]);
            float o8[8] = {oa.x,oa.y,oa.z,oa.w,obv.x,obv.y,obv.z,obv.w};
            float ss = 0.f;
            #pragma unroll
            for (int j = 0; j < 8; j++) ss += o8[j]*o8[j];
            ss += __shfl_xor_sync(0xFFFFFFFFu, ss, 4, 8);
            ss += __shfl_xor_sync(0xFFFFFFFFu, ss, 2, 8);
            ss += __shfl_xor_sync(0xFFFFFFFFu, ss, 1, 8);
            float inv = rsqrtf(ss * (1.f/64.f) + 1e-5f);
            int l = lbase + t;
            if (l < L) {
                size_t rb = ((size_t)(n*L + l))*1024 + 768 + h*64 + dv0;
                float4 r0 = *reinterpret_cast<const float4*>(&qkvr[rb]);
                float4 r1 = *reinterpret_cast<const float4*>(&qkvr[rb + 4]);
                float4 g0 = *reinterpret_cast<const float4*>(&gnp[h*64 + dv0]);
                float4 g1 = *reinterpret_cast<const float4*>(&gnp[h*64 + dv0 + 4]);
                float rr[8] = {r0.x,r0.y,r0.z,r0.w,r1.x,r1.y,r1.z,r1.w};
                float gg[8] = {g0.x,g0.y,g0.z,g0.w,g1.x,g1.y,g1.z,g1.w};
                float res[8];
                #pragma unroll
                for (int j = 0; j < 8; j++)
                    res[j] = o8[j] * inv * gg[j] * (rr[j] / (1.f + __expf(-rr[j])));
                uint32_t hq[4], lq[4];
                #pragma unroll
                for (int j = 0; j < 4; j++) bsplit2(res[2*j], res[2*j+1], hq[j], lq[j]);
                size_t o = ((size_t)(n*L + l)*256 + h*64 + dv0) >> 1;
                *reinterpret_cast<uint4*>(reinterpret_cast<uint32_t*>(ogh) + o)
                    = make_uint4(hq[0], hq[1], hq[2], hq[3]);
                *reinterpret_cast<uint4*>(reinterpret_cast<uint32_t*>(ogl) + o)
                    = make_uint4(lq[0], lq[1], lq[2], lq[3]);
            }
        }
        // S update
        {
            const int mk0 = 16*(w & 3);
            const int nb  = 32*(w >> 2);
            float dd[4][4];
            #pragma unroll
            for (int i = 0; i < 4; i++)
                #pragma unroll
                for (int j = 0; j < 4; j++) dd[i][j] = 0.f;
            #pragma unroll
            for (int ks = 0; ks < 2; ks++) {
                uint32_t kh[4], kl[4];
                uint32_t aoff = SWZ((ks*16 + ((lane >> 3) >> 1)*8 + (lane & 7))*128
                                    + (mk0 + ((lane >> 3) & 1)*8)*2);
                ldm4t(kh, sb + G_KH + aoff);
                ldm4t(kl, sb + G_KL + aoff);
                #pragma unroll
                for (int np = 0; np < 2; np++) {
                    uint32_t vh[4], vl[4];
                    uint32_t boff = SWZ((ks*16 + ((lane >> 3) & 1)*8 + (lane & 7))*128
                                        + (nb + 16*np + (lane >> 4)*8)*2);
                    ldm4t(vh, sb + G_VH + boff);
                    ldm4t(vl, sb + G_VL + boff);
                    mma16816(dd[np*2],   kh, vh[0], vh[1]);
                    mma16816(dd[np*2],   kh, vl[0], vl[1]);
                    mma16816(dd[np*2],   kl, vh[0], vh[1]);
                    mma16816(dd[np*2+1], kh, vh[2], vh[3]);
                    mma16816(dd[np*2+1], kh, vl[2], vl[3]);
                    mma16816(dd[np*2+1], kl, vh[2], vh[3]);
                }
            }
            int r0 = mk0 + (lane >> 2);
            float e0 = __expf(glf[r0]);
            float e1 = __expf(glf[r0 + 8]);
            #pragma unroll
            for (int tile = 0; tile < 4; tile++) {
                int cc = nb + ((tile >> 1) * 16) + ((tile & 1) * 8) + 2*(lane & 3);
                float2 s0 = *reinterpret_cast<float2*>(&S32[r0*68 + cc]);
                s0.x = e0*(s0.x + dd[tile][0]);
                s0.y = e0*(s0.y + dd[tile][1]);
                *reinterpret_cast<float2*>(&S32[r0*68 + cc]) = s0;
                float2 s1 = *reinterpret_cast<float2*>(&S32[(r0+8)*68 + cc]);
                s1.x = e1*(s1.x + dd[tile][2]);
                s1.y = e1*(s1.y + dd[tile][3]);
                *reinterpret_cast<float2*>(&S32[(r0+8)*68 + cc]) = s1;
                uint32_t hp, lp;
                bsplit2(s0.x, s0.y, hp, lp);
                *reinterpret_cast<uint32_t*>(smem + G_SH + SWZ(r0*128 + cc*2)) = hp;
                *reinterpret_cast<uint32_t*>(smem + G_SL + SWZ(r0*128 + cc*2)) = lp;
                bsplit2(s1.x, s1.y, hp, lp);
                *reinterpret_cast<uint32_t*>(smem + G_SH + SWZ((r0+8)*128 + cc*2)) = hp;
                *reinterpret_cast<uint32_t*>(smem + G_SL + SWZ((r0+8)*128 + cc*2)) = lp;
            }
        }
        __syncthreads();
    }
}

__global__ void combine_kernel(const float* __restrict__ d01, const float* __restrict__ ctb,
                               const float* __restrict__ resid, float* __restrict__ out, int pass)
{
    int idx = blockIdx.x * blockDim.x + threadIdx.x;
    if (idx >= ELEMS) return;
    int q = idx & 127, t = (idx >> 7) & 255, c = (idx >> 15) & 63, b = idx >> 21;
    float acc = resid[idx] + ctb[c];
    if (pass == 0) {
        int n = b*256 + t;
        if (q < 127) acc += d01[((size_t)n*127 + q    )*128 + 2*c];
        if (q >= 1)  acc += d01[((size_t)n*127 + q - 1)*128 + 2*c + 1];
    } else {
        int n = b*128 + q;
        if (t < 255) acc += d01[((size_t)n*255 + t    )*128 + 2*c];
        if (t >= 1)  acc += d01[((size_t)n*255 + t - 1)*128 + 2*c + 1];
    }
    out[idx] = acc;
}

struct WPtrs {
    __nv_bfloat16 *wpT_h, *wpT_l, *wggT_h, *wggT_l, *wfT_h, *wfT_l, *fh, *fl, *ogh, *ogl;
};
constexpr int HSM2 = 131072;
constexpr int LN1SM = 9*64*33*4;   // 76032

static void run_pass(const float* input, const float* gamma, const float* beta,
                     const float* Wq, const float* Wk, const float* Wv,
                     const float* Wg1, const float* Wg2, const float* Wr,
                     const float* gn, const float* Wo,
                     const float* ctw, const float* ctb,
                     const float* resid, float* out,
                     float* A, const WPtrs& W, int pass)
{
    const int N   = pass == 0 ? 1024 : 512;
    const int L   = pass == 0 ? 127  : 255;
    const int nc  = pass == 0 ? 4    : 8;
    const int tok = N * L;
    const int Mt  = tok / 128;

    float* qkvr = A + OF_QKVR;
    float* gk   = A + OF_GK;
    float* d01  = A + OF_D01;

    packT_kernel<<<512, 256>>>(Wq, Wk, Wv, Wr, W.wpT_h, W.wpT_l);
    wgg_fused<<<128, 256>>>(Wg1, Wg2, W.wggT_h, W.wggT_l);
    wf_fused<<<128, 256>>>(Wo, ctw, W.wfT_h, W.wfT_l);
    if (pass == 0) lnf0_kernel<<<1024, 128>>>(input, gamma, beta, W.fh, W.fl);
    else           lnf1_kernel<<<512, 256, LN1SM>>>(input, gamma, beta, W.fh, W.fl);
    hg2<0><<<dim3(Mt, 8), 256, HSM2>>>(W.fh, W.fl, W.wpT_h, W.wpT_l, qkvr, tok, 1024, 128);
    hg2<2><<<dim3(Mt, 2), 256, HSM2>>>(W.fh, W.fl, W.wggT_h, W.wggT_l, gk, tok, 256, 128);
    gla_kernel<<<N*4, 256, GSM>>>(qkvr, gk, gn, W.ogh, W.ogl, L, nc);
    hg2<0><<<dim3(Mt, 1), 256, HSM2>>>(W.ogh, W.ogl, W.wfT_h, W.wfT_l, d01, tok, 128, 256);
    combine_kernel<<<CDIV(ELEMS, 256), 256>>>(d01, ctb, resid, out, pass);
}

extern "C" void kernel_launch(void* const* d_in, const int* in_sizes, int n_in,
                              void* d_out, int out_size)
{
    const float* x = (const float*)d_in[0];
    auto P = [&](int i) { return (const float*)d_in[i]; };

    float* arena = nullptr;
    cudaGetSymbolAddress((void**)&arena, g_arena);
    float* y4 = arena + OF_Y4;

    WPtrs W;
    cudaGetSymbolAddress((void**)&W.wpT_h,  g_wpT_h);
    cudaGetSymbolAddress((void**)&W.wpT_l,  g_wpT_l);
    cudaGetSymbolAddress((void**)&W.wggT_h, g_wggT_h);
    cudaGetSymbolAddress((void**)&W.wggT_l, g_wggT_l);
    cudaGetSymbolAddress((void**)&W.wfT_h,  g_wfT_h);
    cudaGetSymbolAddress((void**)&W.wfT_l,  g_wfT_l);
    cudaGetSymbolAddress((void**)&W.fh,     g_fh);
    cudaGetSymbolAddress((void**)&W.fl,     g_fl);
    cudaGetSymbolAddress((void**)&W.ogh,    g_ogh);
    cudaGetSymbolAddress((void**)&W.ogl,    g_ogl);

    cudaFuncSetAttribute(hg2<0>, cudaFuncAttributeMaxDynamicSharedMemorySize, HSM2);
    cudaFuncSetAttribute(hg2<2>, cudaFuncAttributeMaxDynamicSharedMemorySize, HSM2);
    cudaFuncSetAttribute(gla_kernel,  cudaFuncAttributeMaxDynamicSharedMemorySize, GSM);
    cudaFuncSetAttribute(lnf1_kernel, cudaFuncAttributeMaxDynamicSharedMemorySize, LN1SM);

    run_pass(x, P(2), P(3), P(4), P(5), P(6), P(7), P(8), P(9), P(10), P(11), P(12), P(13),
             x, y4, arena, W, 0);
    run_pass(y4, P(14), P(15), P(16), P(17), P(18), P(19), P(20), P(21), P(22), P(23), P(24), P(25),
             y4, (float*)d_out, arena, W, 1);
}

// round 10
// speedup vs baseline: 1.9597x; 1.0105x over previous
#include <cuda_runtime.h>
#include <cuda_bf16.h>
#include <math.h>
#include <stdint.h>

#define CDIV(a,b) (((a)+(b)-1)/(b))
typedef unsigned long long ull;

constexpr int MAXTOK = 130560;
constexpr int ELEMS  = 4*64*256*128;

constexpr size_t OF_QKVR = 0;
constexpr size_t OF_GK   = OF_QKVR + (size_t)MAXTOK*1024;
constexpr size_t OF_D01  = OF_GK   + (size_t)MAXTOK*256;
constexpr size_t OF_Y4   = OF_D01  + (size_t)MAXTOK*128;
constexpr size_t ARENA_TOTAL = OF_Y4 + (size_t)ELEMS;

__device__ __align__(128) float g_arena[ARENA_TOTAL];
__device__ __align__(128) __nv_bfloat16 g_fh[(size_t)MAXTOK*128];
__device__ __align__(128) __nv_bfloat16 g_fl[(size_t)MAXTOK*128];
__device__ __align__(128) __nv_bfloat16 g_ogh[(size_t)MAXTOK*256];
__device__ __align__(128) __nv_bfloat16 g_ogl[(size_t)MAXTOK*256];
__device__ __align__(128) __nv_bfloat16 g_wcat_h[1280*128];   // wp (0-1023) | wgg (1024-1279)
__device__ __align__(128) __nv_bfloat16 g_wcat_l[1280*128];
__device__ __align__(128) __nv_bfloat16 g_wfT_h[128*256];
__device__ __align__(128) __nv_bfloat16 g_wfT_l[128*256];

__device__ __forceinline__ void bsplit(float x, __nv_bfloat16& h, __nv_bfloat16& l) {
    h = __float2bfloat16_rn(x);
    l = __float2bfloat16_rn(x - __bfloat162float(h));
}
__device__ __forceinline__ uint32_t pkbf(float x, float y) {
    uint32_t r; asm("cvt.rn.bf16x2.f32 %0, %1, %2;" : "=r"(r) : "f"(y), "f"(x)); return r;
}
__device__ __forceinline__ void bsplit2(float x0, float x1, uint32_t& hp, uint32_t& lp) {
    hp = pkbf(x0, x1);
    float h0 = __uint_as_float(hp << 16);
    float h1 = __uint_as_float(hp & 0xFFFF0000u);
    lp = pkbf(x0 - h0, x1 - h1);
}

// ---------------------------------------------------------------------------
// Fused weight prep: blocks 0-511 packT(q/k/v/r -> wcat rows 0-1023),
// blocks 512-639 wgg = Wg1@Wg2 ^T (wcat rows 1024-1279),
// blocks 640-767 wf = (Wo@ctw)^T.
// ---------------------------------------------------------------------------
__global__ void prep_kernel(const float* __restrict__ Wq, const float* __restrict__ Wk,
                            const float* __restrict__ Wv, const float* __restrict__ Wr,
                            const float* __restrict__ Wg1, const float* __restrict__ Wg2,
                            const float* __restrict__ Wo, const float* __restrict__ ctw,
                            __nv_bfloat16* __restrict__ wch, __nv_bfloat16* __restrict__ wcl,
                            __nv_bfloat16* __restrict__ wfh, __nv_bfloat16* __restrict__ wfl)
{
    const int blk = blockIdx.x;
    if (blk < 512) {
        int idx = blk * 256 + threadIdx.x;                    // 1024*128
        int n = idx >> 7, k = idx & 127;
        int grp = n >> 8, nn = n & 255;
        const float* W = (grp == 0) ? Wq : (grp == 1) ? Wk : (grp == 2) ? Wv : Wr;
        float x = W[k*256 + nn] * ((grp == 0) ? 0.125f : 1.f);
        __nv_bfloat16 h, l; bsplit(x, h, l);
        wch[idx] = h; wcl[idx] = l;
    } else if (blk < 640) {
        int idx = (blk - 512) * 256 + threadIdx.x;            // 256*128
        int n = idx >> 7, k = idx & 127;
        float s = 0.f;
        #pragma unroll
        for (int j = 0; j < 32; j++) s += __ldg(&Wg1[k*32 + j]) * __ldg(&Wg2[j*256 + n]);
        __nv_bfloat16 h, l; bsplit(s, h, l);
        wch[1024*128 + idx] = h; wcl[1024*128 + idx] = l;
    } else {
        int idx = (blk - 640) * 256 + threadIdx.x;            // 128*256
        int n = idx >> 8, k = idx & 255;
        float s = 0.f;
        #pragma unroll 8
        for (int j = 0; j < 128; j++) s += __ldg(&Wo[k*128 + j]) * __ldg(&ctw[j*128 + n]);
        __nv_bfloat16 h, l; bsplit(s, h, l);
        wfh[idx] = h; wfl[idx] = l;
    }
}

__device__ __forceinline__ uint32_t s2u(const void* p) {
    uint32_t a;
    asm("{ .reg .u64 t; cvta.to.shared.u64 t, %1; cvt.u32.u64 %0, t; }" : "=r"(a) : "l"(p));
    return a;
}
#define SWZ(x) ((x) ^ (((x) >> 3) & 0x70))
__device__ __forceinline__ void ldm4(uint32_t* r, uint32_t addr) {
    asm volatile("ldmatrix.sync.aligned.m8n8.x4.shared.b16 {%0,%1,%2,%3}, [%4];"
        : "=r"(r[0]), "=r"(r[1]), "=r"(r[2]), "=r"(r[3]) : "r"(addr));
}
__device__ __forceinline__ void ldm4t(uint32_t* r, uint32_t addr) {
    asm volatile("ldmatrix.sync.aligned.m8n8.x4.trans.shared.b16 {%0,%1,%2,%3}, [%4];"
        : "=r"(r[0]), "=r"(r[1]), "=r"(r[2]), "=r"(r[3]) : "r"(addr));
}
__device__ __forceinline__ void mma16816(float* d, const uint32_t* a, uint32_t b0, uint32_t b1) {
    asm volatile("mma.sync.aligned.m16n8k16.row.col.f32.bf16.bf16.f32 "
        "{%0,%1,%2,%3}, {%4,%5,%6,%7}, {%8,%9}, {%0,%1,%2,%3};"
        : "+f"(d[0]), "+f"(d[1]), "+f"(d[2]), "+f"(d[3])
        : "r"(a[0]), "r"(a[1]), "r"(a[2]), "r"(a[3]), "r"(b0), "r"(b1));
}
#define CPA16(dst, src) \
    asm volatile("cp.async.cg.shared.global [%0], [%1], 16;" :: "r"(dst), "l"(src))

// ---------------------------------------------------------------------------
// Shared mainloop for bf16-split GEMMs (validated R8 addressing).
// Accumulates into d[2][8][4] over K chunks of 64.
// ---------------------------------------------------------------------------
struct GemmCtx {
    uint32_t sb; int tid, lane, w, m0w, n0w, lrow, lk8;
};
__device__ __forceinline__ void gemm_main(
    GemmCtx& g, float d[2][8][4],
    const __nv_bfloat16* Ah, const __nv_bfloat16* Al,
    const __nv_bfloat16* Bh, const __nv_bfloat16* Bl,
    int m0, int bn0, int K)
{
    auto issue = [&](int ch, int st) {
        const int kc0 = ch << 6;
        const uint32_t sbase = g.sb + st*65536;
        #pragma unroll
        for (int it = 0; it < 4; it++) {
            int i = g.tid + it*256;
            int r = i >> 3, gg = i & 7;
            uint32_t doff = SWZ(r*128 + gg*16);
            size_t aoff = (size_t)(m0 + r)*K + kc0 + gg*8;
            size_t boff = (size_t)(bn0 + r)*K + kc0 + gg*8;
            CPA16(sbase +         doff, Ah + aoff);
            CPA16(sbase + 16384 + doff, Al + aoff);
            CPA16(sbase + 32768 + doff, Bh + boff);
            CPA16(sbase + 49152 + doff, Bl + boff);
        }
        asm volatile("cp.async.commit_group;" ::: "memory");
    };
    const int nch = K >> 6;
    issue(0, 0);
    for (int ch = 0; ch < nch; ch++) {
        const bool nxt = (ch + 1) < nch;
        if (nxt) issue(ch + 1, (ch + 1) & 1);
        if (nxt) asm volatile("cp.async.wait_group 1;" ::: "memory");
        else     asm volatile("cp.async.wait_group 0;" ::: "memory");
        __syncthreads();
        const uint32_t sbase = g.sb + (ch & 1)*65536;
        #pragma unroll
        for (int ks = 0; ks < 4; ks++) {
            const int kcol = ks*16 + g.lk8;
            uint32_t ah[2][4], al2[2][4], bb[4][4];
            #pragma unroll
            for (int mt = 0; mt < 2; mt++) {
                uint32_t off = SWZ((g.m0w + mt*16 + g.lrow)*128 + kcol*2);
                ldm4(ah[mt],  sbase + off);
                ldm4(al2[mt], sbase + 16384 + off);
            }
            #pragma unroll
            for (int nt2 = 0; nt2 < 4; nt2++) {
                uint32_t off = SWZ((g.n0w + nt2*16 + g.lrow)*128 + kcol*2);
                ldm4(bb[nt2], sbase + 32768 + off);
            }
            #pragma unroll
            for (int mt = 0; mt < 2; mt++)
                #pragma unroll
                for (int nt = 0; nt < 8; nt++) {
                    uint32_t b0 = (nt & 1) ? bb[nt>>1][1] : bb[nt>>1][0];
                    uint32_t b1 = (nt & 1) ? bb[nt>>1][3] : bb[nt>>1][2];
                    mma16816(d[mt][nt], ah[mt],  b0, b1);
                    mma16816(d[mt][nt], al2[mt], b0, b1);
                }
            #pragma unroll
            for (int nt2 = 0; nt2 < 4; nt2++) {
                uint32_t off = SWZ((g.n0w + nt2*16 + g.lrow)*128 + kcol*2);
                ldm4(bb[nt2], sbase + 49152 + off);
            }
            #pragma unroll
            for (int mt = 0; mt < 2; mt++)
                #pragma unroll
                for (int nt = 0; nt < 8; nt++) {
                    uint32_t b0 = (nt & 1) ? bb[nt>>1][1] : bb[nt>>1][0];
                    uint32_t b1 = (nt & 1) ? bb[nt>>1][3] : bb[nt>>1][2];
                    mma16816(d[mt][nt], ah[mt], b0, b1);
                }
        }
        __syncthreads();
    }
}
__device__ __forceinline__ GemmCtx mk_ctx(uint32_t sb) {
    GemmCtx g;
    g.tid = threadIdx.x; g.lane = g.tid & 31; g.w = g.tid >> 5;
    g.m0w = (g.w & 3) * 32; g.n0w = (g.w >> 2) * 64;
    g.lrow = g.lane & 15; g.lk8 = (g.lane >> 4) << 3;
    g.sb = sb;
    return g;
}

// Merged qkvr+gk GEMM: blockIdx.y<8 -> qkvr (N=1024), else gk (N=256, logsig epi)
__global__ void __launch_bounds__(256, 1)
hg2c(const __nv_bfloat16* __restrict__ Ah, const __nv_bfloat16* __restrict__ Al,
     const __nv_bfloat16* __restrict__ Bh, const __nv_bfloat16* __restrict__ Bl,
     float* __restrict__ Cq, float* __restrict__ Cg, int M)
{
    extern __shared__ char smem[];
    GemmCtx g = mk_ctx(s2u(smem));
    const int m0 = blockIdx.x * 128;
    float d[2][8][4];
    #pragma unroll
    for (int mt = 0; mt < 2; mt++)
        #pragma unroll
        for (int nt = 0; nt < 8; nt++)
            #pragma unroll
            for (int u = 0; u < 4; u++) d[mt][nt][u] = 0.f;

    gemm_main(g, d, Ah, Al, Bh, Bl, m0, blockIdx.y * 128, 128);

    const bool isgk = blockIdx.y >= 8;
    float* C   = isgk ? Cg : Cq;
    const int Nn = isgk ? 256 : 1024;
    const int nb = (isgk ? (blockIdx.y - 8) : blockIdx.y) * 128;
    const int er = g.lane >> 2, ec = (g.lane & 3) * 2;
    #pragma unroll
    for (int mt = 0; mt < 2; mt++) {
        #pragma unroll
        for (int nt = 0; nt < 8; nt++) {
            float v[4] = {d[mt][nt][0], d[mt][nt][1], d[mt][nt][2], d[mt][nt][3]};
            if (isgk) {
                #pragma unroll
                for (int u = 0; u < 4; u++)
                    v[u] = (fminf(v[u], 0.f) - log1pf(__expf(-fabsf(v[u])))) * (1.f/32.f);
            }
            size_t m = (size_t)(m0 + g.m0w + mt*16 + er);
            int    n = nb + g.n0w + nt*8 + ec;
            *reinterpret_cast<float2*>(&C[m*Nn + n])       = make_float2(v[0], v[1]);
            *reinterpret_cast<float2*>(&C[(m + 8)*Nn + n]) = make_float2(v[2], v[3]);
        }
    }
}

// d01 GEMM (og @ wf)
__global__ void __launch_bounds__(256, 1)
hg2(const __nv_bfloat16* __restrict__ Ah, const __nv_bfloat16* __restrict__ Al,
    const __nv_bfloat16* __restrict__ Bh, const __nv_bfloat16* __restrict__ Bl,
    float* __restrict__ C, int M, int N, int K)
{
    extern __shared__ char smem[];
    GemmCtx g = mk_ctx(s2u(smem));
    const int m0 = blockIdx.x * 128;
    const int n0 = blockIdx.y * 128;
    float d[2][8][4];
    #pragma unroll
    for (int mt = 0; mt < 2; mt++)
        #pragma unroll
        for (int nt = 0; nt < 8; nt++)
            #pragma unroll
            for (int u = 0; u < 4; u++) d[mt][nt][u] = 0.f;

    gemm_main(g, d, Ah, Al, Bh, Bl, m0, n0, K);

    const int er = g.lane >> 2, ec = (g.lane & 3) * 2;
    #pragma unroll
    for (int mt = 0; mt < 2; mt++) {
        #pragma unroll
        for (int nt = 0; nt < 8; nt++) {
            size_t m = (size_t)(m0 + g.m0w + mt*16 + er);
            int    n = n0 + g.n0w + nt*8 + ec;
            *reinterpret_cast<float2*>(&C[m*N + n])       = make_float2(d[mt][nt][0], d[mt][nt][1]);
            *reinterpret_cast<float2*>(&C[(m + 8)*N + n]) = make_float2(d[mt][nt][2], d[mt][nt][3]);
        }
    }
}

// ---------------------------------------------------------------------------
// Fused LN + unfold (validated R9)
// ---------------------------------------------------------------------------
__global__ void __launch_bounds__(128)
lnf0_kernel(const float* __restrict__ x, const float* __restrict__ gamma,
            const float* __restrict__ beta,
            __nv_bfloat16* __restrict__ fh, __nv_bfloat16* __restrict__ fl)
{
    __shared__ float U[64][129];
    const int tid = threadIdx.x;
    const int b = blockIdx.x >> 8, t = blockIdx.x & 255;
    const int n = blockIdx.x;
    #pragma unroll 8
    for (int c = 0; c < 64; c++)
        U[c][tid] = x[(((size_t)b*64 + c)*256 + t)*128 + tid];
    __syncthreads();
    float sum = 0.f, sq = 0.f;
    #pragma unroll 8
    for (int c = 0; c < 64; c++) { float v = U[c][tid]; sum += v; sq += v*v; }
    float mu  = sum * (1.f/64.f);
    float inv = rsqrtf(sq * (1.f/64.f) - mu*mu + 1e-5f);
    #pragma unroll 8
    for (int c = 0; c < 64; c++)
        U[c][tid] = (U[c][tid] - mu) * inv * gamma[c] + beta[c];
    __syncthreads();
    uint32_t* fhp = reinterpret_cast<uint32_t*>(fh);
    uint32_t* flp = reinterpret_cast<uint32_t*>(fl);
    #pragma unroll 4
    for (int it = 0; it < 64; it++) {
        int idx = it*128 + tid;
        int l = idx >> 6, c = idx & 63;
        if (l >= 127) continue;
        uint32_t hp, lp;
        bsplit2(U[c][l], U[c][l+1], hp, lp);
        size_t o = (size_t)(n*127 + l)*64 + c;
        fhp[o] = hp; flp[o] = lp;
    }
}

__global__ void __launch_bounds__(256)
lnf1_kernel(const float* __restrict__ x, const float* __restrict__ gamma,
            const float* __restrict__ beta,
            __nv_bfloat16* __restrict__ fh, __nv_bfloat16* __restrict__ fl)
{
    extern __shared__ float Us[];
    const int tid = threadIdx.x;
    const int tt = blockIdx.x & 31;
    const int qt = (blockIdx.x >> 5) & 3;
    const int b  = blockIdx.x >> 7;
    const int t0 = tt*8, q0 = qt*32;
    auto UI = [&](int tl, int c, int q) -> float& { return Us[(tl*64 + c)*33 + q]; };

    #pragma unroll
    for (int it = 0; it < 72; it++) {
        int idx = it*256 + tid;
        int q = idx & 31, c = (idx >> 5) & 63, tl = idx >> 11;
        int t = t0 + tl;
        UI(tl, c, q) = (t < 256) ? x[(((size_t)b*64 + c)*256 + t)*128 + q0 + q] : 0.f;
    }
    __syncthreads();
    for (int pair = tid; pair < 288; pair += 256) {
        int tl = pair >> 5, q = pair & 31;
        float sum = 0.f, sq = 0.f;
        #pragma unroll 8
        for (int c = 0; c < 64; c++) { float v = UI(tl, c, q); sum += v; sq += v*v; }
        float mu  = sum * (1.f/64.f);
        float inv = rsqrtf(sq * (1.f/64.f) - mu*mu + 1e-5f);
        #pragma unroll 8
        for (int c = 0; c < 64; c++)
            UI(tl, c, q) = (UI(tl, c, q) - mu) * inv * gamma[c] + beta[c];
    }
    __syncthreads();
    uint32_t* fhp = reinterpret_cast<uint32_t*>(fh);
    uint32_t* flp = reinterpret_cast<uint32_t*>(fl);
    #pragma unroll 4
    for (int it = 0; it < 64; it++) {
        int idx = it*256 + tid;
        int c = idx & 63, tl = (idx >> 6) & 7, q = idx >> 9;
        int l = t0 + tl;
        if (l >= 255) continue;
        uint32_t hp, lp;
        bsplit2(UI(tl, c, q), UI(tl+1, c, q), hp, lp);
        size_t o = ((size_t)(b*128 + q0 + q)*255 + l)*64 + c;
        fhp[o] = hp; flp[o] = lp;
    }
}

// ---------------------------------------------------------------------------
// GLA v4 (validated) — og emitted as bf16 hi/lo
// ---------------------------------------------------------------------------
constexpr int G_SH = 0,     G_SL = 8192,  G_S32 = 16384;
constexpr int G_QH = 33792, G_QL = 37888, G_KH = 41984, G_KL = 46080;
constexpr int G_VH = 50176, G_VL = 54272, G_AH = 58368, G_AL = 62464;
constexpr int G_U  = 66560, G_GL = 75264, GSM = 75520;

__global__ void __launch_bounds__(256)
gla_kernel(const float* __restrict__ qkvr, const float* __restrict__ gkb,
           const float* __restrict__ gnp,
           __nv_bfloat16* __restrict__ ogh, __nv_bfloat16* __restrict__ ogl,
           int L, int nc)
{
    extern __shared__ char smem[];
    const uint32_t sb = s2u(smem);
    float* Uf  = reinterpret_cast<float*>(smem + G_U);
    float* S32 = reinterpret_cast<float*>(smem + G_S32);
    float* glf = reinterpret_cast<float*>(smem + G_GL);
    const int n = blockIdx.x >> 2, h = blockIdx.x & 3;
    const int tid = threadIdx.x, lane = tid & 31, w = tid >> 5;

    for (int i = tid; i < 33792/4; i += 256) reinterpret_cast<uint32_t*>(smem)[i] = 0u;
    __syncthreads();

    for (int c = 0; c < nc; c++) {
        const int lbase = c * 32;
        #pragma unroll
        for (int r = 0; r < 2; r++) {
            int i = tid + r*256, t = i >> 4, d4 = (i & 15) * 4, l = lbase + t;
            float4 gv = make_float4(0,0,0,0);
            if (l < L)
                gv = *reinterpret_cast<const float4*>(&gkb[((size_t)(n*L + l))*256 + h*64 + d4]);
            *reinterpret_cast<float4*>(&Uf[t*68 + d4]) = gv;
        }
        __syncthreads();
        if (tid < 64) {
            float s = 0.f;
            #pragma unroll
            for (int t = 0; t < 32; t++) { s += Uf[t*68 + tid]; Uf[t*68 + tid] = s; }
            glf[tid] = s;
        }
        __syncthreads();
        #pragma unroll
        for (int r = 0; r < 2; r++) {
            int i = tid + r*256, t = i >> 4, d4 = (i & 15) * 4, l = lbase + t;
            float4 qv = make_float4(0,0,0,0), kv = qv, vv = qv;
            if (l < L) {
                size_t base = ((size_t)(n*L + l))*1024 + h*64 + d4;
                qv = *reinterpret_cast<const float4*>(&qkvr[base]);
                kv = *reinterpret_cast<const float4*>(&qkvr[base + 256]);
                vv = *reinterpret_cast<const float4*>(&qkvr[base + 512]);
                float4 g = *reinterpret_cast<const float4*>(&Uf[t*68 + d4]);
                qv.x *= __expf(g.x);  qv.y *= __expf(g.y);
                qv.z *= __expf(g.z);  qv.w *= __expf(g.w);
                kv.x *= __expf(-g.x); kv.y *= __expf(-g.y);
                kv.z *= __expf(-g.z); kv.w *= __expf(-g.w);
            }
            uint32_t off = SWZ(t*128 + d4*2);
            uint32_t h0, l0, h1, l1;
            bsplit2(qv.x, qv.y, h0, l0); bsplit2(qv.z, qv.w, h1, l1);
            *reinterpret_cast<uint2*>(smem + G_QH + off) = make_uint2(h0, h1);
            *reinterpret_cast<uint2*>(smem + G_QL + off) = make_uint2(l0, l1);
            bsplit2(kv.x, kv.y, h0, l0); bsplit2(kv.z, kv.w, h1, l1);
            *reinterpret_cast<uint2*>(smem + G_KH + off) = make_uint2(h0, h1);
            *reinterpret_cast<uint2*>(smem + G_KL + off) = make_uint2(l0, l1);
            bsplit2(vv.x, vv.y, h0, l0); bsplit2(vv.z, vv.w, h1, l1);
            *reinterpret_cast<uint2*>(smem + G_VH + off) = make_uint2(h0, h1);
            *reinterpret_cast<uint2*>(smem + G_VL + off) = make_uint2(l0, l1);
        }
        __syncthreads();
        // A = QK^T masked
        {
            const int mrow = 16*(w & 1) + (lane & 15);
            const int s0   = 8*(w >> 1);
            uint32_t kbh[2][4], kbl[2][4];
            #pragma unroll
            for (int g = 0; g < 2; g++) {
                uint32_t off = SWZ((s0 + (lane & 7))*128 + (g*32 + (lane >> 3)*8)*2);
                ldm4(kbh[g], sb + G_KH + off);
                ldm4(kbl[g], sb + G_KL + off);
            }
            float dA[4] = {0,0,0,0};
            #pragma unroll
            for (int ks = 0; ks < 4; ks++) {
                uint32_t ah[4], al[4];
                uint32_t aoff = SWZ(mrow*128 + (ks*16 + (lane >> 4)*8)*2);
                ldm4(ah, sb + G_QH + aoff);
                ldm4(al, sb + G_QL + aoff);
                uint32_t b0h = kbh[ks>>1][(ks&1)*2], b1h = kbh[ks>>1][(ks&1)*2+1];
                uint32_t b0l = kbl[ks>>1][(ks&1)*2], b1l = kbl[ks>>1][(ks&1)*2+1];
                mma16816(dA, ah, b0h, b1h);
                mma16816(dA, ah, b0l, b1l);
                mma16816(dA, al, b0h, b1h);
            }
            int r0 = 16*(w & 1) + (lane >> 2);
            int cc = s0 + 2*(lane & 3);
            float v00 = (cc   <= r0  ) ? dA[0] : 0.f;
            float v01 = (cc+1 <= r0  ) ? dA[1] : 0.f;
            float v10 = (cc   <= r0+8) ? dA[2] : 0.f;
            float v11 = (cc+1 <= r0+8) ? dA[3] : 0.f;
            uint32_t hp, lp;
            bsplit2(v00, v01, hp, lp);
            *reinterpret_cast<uint32_t*>(smem + G_AH + SWZ(r0*128 + cc*2)) = hp;
            *reinterpret_cast<uint32_t*>(smem + G_AL + SWZ(r0*128 + cc*2)) = lp;
            bsplit2(v10, v11, hp, lp);
            *reinterpret_cast<uint32_t*>(smem + G_AH + SWZ((r0+8)*128 + cc*2)) = hp;
            *reinterpret_cast<uint32_t*>(smem + G_AL + SWZ((r0+8)*128 + cc*2)) = lp;
        }
        __syncthreads();
        // o = A@V + Q@S(old) -> U
        {
            const int mrow = 16*(w & 1) + (lane & 15);
            const int nv0  = 16*(w >> 1);
            float d0[4] = {0,0,0,0}, d1[4] = {0,0,0,0};
            #pragma unroll
            for (int ks = 0; ks < 2; ks++) {
                uint32_t ah[4], al[4], vh[4], vl[4];
                uint32_t aoff = SWZ(mrow*128 + (ks*16 + (lane >> 4)*8)*2);
                ldm4(ah, sb + G_AH + aoff);
                ldm4(al, sb + G_AL + aoff);
                uint32_t boff = SWZ((ks*16 + ((lane >> 3) & 1)*8 + (lane & 7))*128
                                    + (nv0 + (lane >> 4)*8)*2);
                ldm4t(vh, sb + G_VH + boff);
                ldm4t(vl, sb + G_VL + boff);
                mma16816(d0, ah, vh[0], vh[1]);
                mma16816(d0, ah, vl[0], vl[1]);
                mma16816(d0, al, vh[0], vh[1]);
                mma16816(d1, ah, vh[2], vh[3]);
                mma16816(d1, ah, vl[2], vl[3]);
                mma16816(d1, al, vh[2], vh[3]);
            }
            #pragma unroll
            for (int ks = 0; ks < 4; ks++) {
                uint32_t qh[4], ql[4], sh[4], sl[4];
                uint32_t aoff = SWZ(mrow*128 + (ks*16 + (lane >> 4)*8)*2);
                ldm4(qh, sb + G_QH + aoff);
                ldm4(ql, sb + G_QL + aoff);
                uint32_t boff = SWZ((ks*16 + ((lane >> 3) & 1)*8 + (lane & 7))*128
                                    + (nv0 + (lane >> 4)*8)*2);
                ldm4t(sh, sb + G_SH + boff);
                ldm4t(sl, sb + G_SL + boff);
                mma16816(d0, qh, sh[0], sh[1]);
                mma16816(d0, qh, sl[0], sl[1]);
                mma16816(d0, ql, sh[0], sh[1]);
                mma16816(d1, qh, sh[2], sh[3]);
                mma16816(d1, qh, sl[2], sl[3]);
                mma16816(d1, ql, sh[2], sh[3]);
            }
            int r0 = 16*(w & 1) + (lane >> 2);
            int c0 = nv0 + 2*(lane & 3);
            *reinterpret_cast<float2*>(&Uf[r0*68 + c0])         = make_float2(d0[0], d0[1]);
            *reinterpret_cast<float2*>(&Uf[(r0+8)*68 + c0])     = make_float2(d0[2], d0[3]);
            *reinterpret_cast<float2*>(&Uf[r0*68 + c0 + 8])     = make_float2(d1[0], d1[1]);
            *reinterpret_cast<float2*>(&Uf[(r0+8)*68 + c0 + 8]) = make_float2(d1[2], d1[3]);
        }
        __syncthreads();
        // gate epilogue -> og hi/lo
        {
            int t = tid >> 3, dv0 = (tid & 7) * 8;
            float4 oa = *reinterpret_cast<const float4*>(&Uf[t*68 + dv0]);
            float4 obv = *reinterpret_cast<const float4*>(&Uf[t*68 + dv0 + 4]);
            float o8[8] = {oa.x,oa.y,oa.z,oa.w,obv.x,obv.y,obv.z,obv.w};
            float ss = 0.f;
            #pragma unroll
            for (int j = 0; j < 8; j++) ss += o8[j]*o8[j];
            ss += __shfl_xor_sync(0xFFFFFFFFu, ss, 4, 8);
            ss += __shfl_xor_sync(0xFFFFFFFFu, ss, 2, 8);
            ss += __shfl_xor_sync(0xFFFFFFFFu, ss, 1, 8);
            float inv = rsqrtf(ss * (1.f/64.f) + 1e-5f);
            int l = lbase + t;
            if (l < L) {
                size_t rb = ((size_t)(n*L + l))*1024 + 768 + h*64 + dv0;
                float4 r0 = *reinterpret_cast<const float4*>(&qkvr[rb]);
                float4 r1 = *reinterpret_cast<const float4*>(&qkvr[rb + 4]);
                float4 g0 = *reinterpret_cast<const float4*>(&gnp[h*64 + dv0]);
                float4 g1 = *reinterpret_cast<const float4*>(&gnp[h*64 + dv0 + 4]);
                float rr[8] = {r0.x,r0.y,r0.z,r0.w,r1.x,r1.y,r1.z,r1.w};
                float gg[8] = {g0.x,g0.y,g0.z,g0.w,g1.x,g1.y,g1.z,g1.w};
                float res[8];
                #pragma unroll
                for (int j = 0; j < 8; j++)
                    res[j] = o8[j] * inv * gg[j] * (rr[j] / (1.f + __expf(-rr[j])));
                uint32_t hq[4], lq[4];
                #pragma unroll
                for (int j = 0; j < 4; j++) bsplit2(res[2*j], res[2*j+1], hq[j], lq[j]);
                size_t o = ((size_t)(n*L + l)*256 + h*64 + dv0) >> 1;
                *reinterpret_cast<uint4*>(reinterpret_cast<uint32_t*>(ogh) + o)
                    = make_uint4(hq[0], hq[1], hq[2], hq[3]);
                *reinterpret_cast<uint4*>(reinterpret_cast<uint32_t*>(ogl) + o)
                    = make_uint4(lq[0], lq[1], lq[2], lq[3]);
            }
        }
        // S update
        {
            const int mk0 = 16*(w & 3);
            const int nb  = 32*(w >> 2);
            float dd[4][4];
            #pragma unroll
            for (int i = 0; i < 4; i++)
                #pragma unroll
                for (int j = 0; j < 4; j++) dd[i][j] = 0.f;
            #pragma unroll
            for (int ks = 0; ks < 2; ks++) {
                uint32_t kh[4], kl[4];
                uint32_t aoff = SWZ((ks*16 + ((lane >> 3) >> 1)*8 + (lane & 7))*128
                                    + (mk0 + ((lane >> 3) & 1)*8)*2);
                ldm4t(kh, sb + G_KH + aoff);
                ldm4t(kl, sb + G_KL + aoff);
                #pragma unroll
                for (int np = 0; np < 2; np++) {
                    uint32_t vh[4], vl[4];
                    uint32_t boff = SWZ((ks*16 + ((lane >> 3) & 1)*8 + (lane & 7))*128
                                        + (nb + 16*np + (lane >> 4)*8)*2);
                    ldm4t(vh, sb + G_VH + boff);
                    ldm4t(vl, sb + G_VL + boff);
                    mma16816(dd[np*2],   kh, vh[0], vh[1]);
                    mma16816(dd[np*2],   kh, vl[0], vl[1]);
                    mma16816(dd[np*2],   kl, vh[0], vh[1]);
                    mma16816(dd[np*2+1], kh, vh[2], vh[3]);
                    mma16816(dd[np*2+1], kh, vl[2], vl[3]);
                    mma16816(dd[np*2+1], kl, vh[2], vh[3]);
                }
            }
            int r0 = mk0 + (lane >> 2);
            float e0 = __expf(glf[r0]);
            float e1 = __expf(glf[r0 + 8]);
            #pragma unroll
            for (int tile = 0; tile < 4; tile++) {
                int cc = nb + ((tile >> 1) * 16) + ((tile & 1) * 8) + 2*(lane & 3);
                float2 s0 = *reinterpret_cast<float2*>(&S32[r0*68 + cc]);
                s0.x = e0*(s0.x + dd[tile][0]);
                s0.y = e0*(s0.y + dd[tile][1]);
                *reinterpret_cast<float2*>(&S32[r0*68 + cc]) = s0;
                float2 s1 = *reinterpret_cast<float2*>(&S32[(r0+8)*68 + cc]);
                s1.x = e1*(s1.x + dd[tile][2]);
                s1.y = e1*(s1.y + dd[tile][3]);
                *reinterpret_cast<float2*>(&S32[(r0+8)*68 + cc]) = s1;
                uint32_t hp, lp;
                bsplit2(s0.x, s0.y, hp, lp);
                *reinterpret_cast<uint32_t*>(smem + G_SH + SWZ(r0*128 + cc*2)) = hp;
                *reinterpret_cast<uint32_t*>(smem + G_SL + SWZ(r0*128 + cc*2)) = lp;
                bsplit2(s1.x, s1.y, hp, lp);
                *reinterpret_cast<uint32_t*>(smem + G_SH + SWZ((r0+8)*128 + cc*2)) = hp;
                *reinterpret_cast<uint32_t*>(smem + G_SL + SWZ((r0+8)*128 + cc*2)) = lp;
            }
        }
        __syncthreads();
    }
}

// ---------------------------------------------------------------------------
// combine0 (pass 0): smem-staged, fully coalesced.
// ---------------------------------------------------------------------------
__global__ void __launch_bounds__(256)
combine0_kernel(const float* __restrict__ d01, const float* __restrict__ ctb,
                const float* __restrict__ resid, float* __restrict__ out)
{
    extern __shared__ float sm[];              // [127][129]
    const int tid = threadIdx.x;
    const int n = blockIdx.x;                  // b*256 + t
    const int b = n >> 8, t = n & 255;
    for (int i = tid; i < 127*128; i += 256) {
        int tok = i >> 7, col = i & 127;
        sm[tok*129 + col] = d01[((size_t)n*127 + tok)*128 + col];
    }
    __syncthreads();
    #pragma unroll 4
    for (int i = tid; i < 8192; i += 256) {
        int q = i & 127, c = i >> 7;
        size_t oidx = (((size_t)b*64 + c)*256 + t)*128 + q;
        float acc = resid[oidx] + ctb[c];
        if (q < 127) acc += sm[q*129 + 2*c];
        if (q >= 1)  acc += sm[(q-1)*129 + 2*c + 1];
        out[oidx] = acc;
    }
}

// generic combine (pass 1 only)
__global__ void combine_kernel(const float* __restrict__ d01, const float* __restrict__ ctb,
                               const float* __restrict__ resid, float* __restrict__ out)
{
    int idx = blockIdx.x * blockDim.x + threadIdx.x;
    if (idx >= ELEMS) return;
    int q = idx & 127, t = (idx >> 7) & 255, c = (idx >> 15) & 63, b = idx >> 21;
    float acc = resid[idx] + ctb[c];
    int n = b*128 + q;
    if (t < 255) acc += d01[((size_t)n*255 + t    )*128 + 2*c];
    if (t >= 1)  acc += d01[((size_t)n*255 + t - 1)*128 + 2*c + 1];
    out[idx] = acc;
}

struct WPtrs {
    __nv_bfloat16 *wch, *wcl, *wfT_h, *wfT_l, *fh, *fl, *ogh, *ogl;
};
constexpr int HSM2  = 131072;
constexpr int LN1SM = 9*64*33*4;
constexpr int C0SM  = 127*129*4;

static void run_pass(const float* input, const float* gamma, const float* beta,
                     const float* Wq, const float* Wk, const float* Wv,
                     const float* Wg1, const float* Wg2, const float* Wr,
                     const float* gn, const float* Wo,
                     const float* ctw, const float* ctb,
                     const float* resid, float* out,
                     float* A, const WPtrs& W, int pass)
{
    const int N   = pass == 0 ? 1024 : 512;
    const int L   = pass == 0 ? 127  : 255;
    const int nc  = pass == 0 ? 4    : 8;
    const int tok = N * L;
    const int Mt  = tok / 128;

    float* qkvr = A + OF_QKVR;
    float* gk   = A + OF_GK;
    float* d01  = A + OF_D01;

    prep_kernel<<<768, 256>>>(Wq, Wk, Wv, Wr, Wg1, Wg2, Wo, ctw,
                              W.wch, W.wcl, W.wfT_h, W.wfT_l);
    if (pass == 0) lnf0_kernel<<<1024, 128>>>(input, gamma, beta, W.fh, W.fl);
    else           lnf1_kernel<<<512, 256, LN1SM>>>(input, gamma, beta, W.fh, W.fl);
    hg2c<<<dim3(Mt, 10), 256, HSM2>>>(W.fh, W.fl, W.wch, W.wcl, qkvr, gk, tok);
    gla_kernel<<<N*4, 256, GSM>>>(qkvr, gk, gn, W.ogh, W.ogl, L, nc);
    hg2<<<dim3(Mt, 1), 256, HSM2>>>(W.ogh, W.ogl, W.wfT_h, W.wfT_l, d01, tok, 128, 256);
    if (pass == 0) combine0_kernel<<<1024, 256, C0SM>>>(d01, ctb, resid, out);
    else           combine_kernel<<<CDIV(ELEMS, 256), 256>>>(d01, ctb, resid, out);
}

extern "C" void kernel_launch(void* const* d_in, const int* in_sizes, int n_in,
                              void* d_out, int out_size)
{
    const float* x = (const float*)d_in[0];
    auto P = [&](int i) { return (const float*)d_in[i]; };

    float* arena = nullptr;
    cudaGetSymbolAddress((void**)&arena, g_arena);
    float* y4 = arena + OF_Y4;

    WPtrs W;
    cudaGetSymbolAddress((void**)&W.wch,   g_wcat_h);
    cudaGetSymbolAddress((void**)&W.wcl,   g_wcat_l);
    cudaGetSymbolAddress((void**)&W.wfT_h, g_wfT_h);
    cudaGetSymbolAddress((void**)&W.wfT_l, g_wfT_l);
    cudaGetSymbolAddress((void**)&W.fh,    g_fh);
    cudaGetSymbolAddress((void**)&W.fl,    g_fl);
    cudaGetSymbolAddress((void**)&W.ogh,   g_ogh);
    cudaGetSymbolAddress((void**)&W.ogl,   g_ogl);

    cudaFuncSetAttribute(hg2c, cudaFuncAttributeMaxDynamicSharedMemorySize, HSM2);
    cudaFuncSetAttribute(hg2,  cudaFuncAttributeMaxDynamicSharedMemorySize, HSM2);
    cudaFuncSetAttribute(gla_kernel,  cudaFuncAttributeMaxDynamicSharedMemorySize, GSM);
    cudaFuncSetAttribute(lnf1_kernel, cudaFuncAttributeMaxDynamicSharedMemorySize, LN1SM);
    cudaFuncSetAttribute(combine0_kernel, cudaFuncAttributeMaxDynamicSharedMemorySize, C0SM);

    run_pass(x, P(2), P(3), P(4), P(5), P(6), P(7), P(8), P(9), P(10), P(11), P(12), P(13),
             x, y4, arena, W, 0);
    run_pass(y4, P(14), P(15), P(16), P(17), P(18), P(19), P(20), P(21), P(22), P(23), P(24), P(25),
             y4, (float*)d_out, arena, W, 1);
}